// round 4
// baseline (speedup 1.0000x reference)
#include <cuda_runtime.h>
#include <cstddef>

#define NN   100000
#define NE   3200000
#define FIN  10
#define HID  30
#define NCLS 4
#define S1   12   // padded stride for layer-1 T buffers (10 -> 12 floats = 48B, 16B-multiple)
#define S2   32   // padded stride for layer-2 / accumulator buffers (30 -> 32 floats = 128B)

// ---------------- scratch (static device globals; no runtime allocation) ----
// __align__(16): required for float4 loads and red.global.add.v4.f32.
__device__ __align__(16) float g_deg[NN];
__device__ __align__(16) float g_norm[NE];
__device__ __align__(16) float g_T0[NN * S1];
__device__ __align__(16) float g_T1[NN * S1];
__device__ __align__(16) float g_T2[NN * S1];
__device__ __align__(16) float g_A2[NN * S2];
__device__ __align__(16) float g_B2[NN * S2];
__device__ __align__(16) float g_C2[NN * S2];
__device__ __align__(16) float g_O1[NN * S2];
__device__ __align__(16) float g_O2[NN * S2];

// ---------------- vector reductions (sm_90+): no-return global float adds ---
__device__ __forceinline__ void red4(float* addr, float x, float y, float z, float w) {
    asm volatile("red.global.add.v4.f32 [%0], {%1,%2,%3,%4};"
                 :: "l"(addr), "f"(x), "f"(y), "f"(z), "f"(w) : "memory");
}
__device__ __forceinline__ void red2(float* addr, float x, float y) {
    asm volatile("red.global.add.v2.f32 [%0], {%1,%2};"
                 :: "l"(addr), "f"(x), "f"(y) : "memory");
}

// ---------------- norm pipeline --------------------------------------------
__global__ void k_zero_deg() {
    int i = blockIdx.x * blockDim.x + threadIdx.x;
    if (i < NN) g_deg[i] = 0.f;
}

__global__ void k_deg(const int* __restrict__ src, const int* __restrict__ dst,
                      const float* __restrict__ w) {
    int e = blockIdx.x * blockDim.x + threadIdx.x;
    if (e >= NE) return;
    int s = src[e];
    if (s != dst[e]) atomicAdd(&g_deg[s], w[e]);
}

__global__ void k_norm(const int* __restrict__ src, const int* __restrict__ dst,
                       const float* __restrict__ w) {
    int e = blockIdx.x * blockDim.x + threadIdx.x;
    if (e >= NE) return;
    int s = src[e], d = dst[e];
    float we = (s == d) ? 0.f : w[e];
    float ds = g_deg[s], dd = g_deg[d];
    float is = (ds > 0.f) ? rsqrtf(ds) : 0.f;
    float id = (dd > 0.f) ? rsqrtf(dd) : 0.f;
    g_norm[e] = -is * we * id;
}

// ---------------- layer 1 init: T0 = pad(x), T1 = 0, O1 = x @ W1[0] ---------
__global__ void k_l1_init(const float* __restrict__ x, const float* __restrict__ W0) {
    __shared__ float sW[FIN * HID];
    for (int i = threadIdx.x; i < FIN * HID; i += blockDim.x) sW[i] = W0[i];
    __syncthreads();
    int n = blockIdx.x * blockDim.x + threadIdx.x;
    if (n >= NN) return;
    float t[FIN];
    const float* xr = x + (size_t)n * FIN;
#pragma unroll
    for (int i = 0; i < FIN; i++) t[i] = xr[i];
    float* a = g_T0 + (size_t)n * S1;
#pragma unroll
    for (int i = 0; i < FIN; i++) a[i] = t[i];
    a[10] = 0.f; a[11] = 0.f;
    float4* b = (float4*)(g_T1 + (size_t)n * S1);
#pragma unroll
    for (int i = 0; i < 3; i++) b[i] = make_float4(0.f, 0.f, 0.f, 0.f);
    float* o = g_O1 + (size_t)n * S2;
#pragma unroll
    for (int j = 0; j < HID; j++) {
        float acc = 0.f;
#pragma unroll
        for (int i = 0; i < FIN; i++) acc += t[i] * sW[i * HID + j];
        o[j] = acc;
    }
}

// ---------------- scatter props: hout[dst] += scale*norm * hin[src] ---------
__global__ void k_prop10(const float* __restrict__ hin, float* __restrict__ hout,
                         const int* __restrict__ src, const int* __restrict__ dst,
                         float scale) {
    int e = blockIdx.x * blockDim.x + threadIdx.x;
    if (e >= NE) return;
    float c = g_norm[e] * scale;
    if (c == 0.f) return;
    int s = src[e], d = dst[e];
    const float* p = hin + (size_t)s * S1;
    float4 a = *(const float4*)(p);
    float4 b = *(const float4*)(p + 4);
    float2 q = *(const float2*)(p + 8);
    float* o = hout + (size_t)d * S1;
    red4(o,     c * a.x, c * a.y, c * a.z, c * a.w);
    red4(o + 4, c * b.x, c * b.y, c * b.z, c * b.w);
    red2(o + 8, c * q.x, c * q.y);
}

__global__ void k_prop30(const float* __restrict__ hin, float* __restrict__ hout,
                         const int* __restrict__ src, const int* __restrict__ dst,
                         float scale) {
    int e = blockIdx.x * blockDim.x + threadIdx.x;
    if (e >= NE) return;
    float c = g_norm[e] * scale;
    if (c == 0.f) return;
    int s = src[e], d = dst[e];
    const float* p = hin + (size_t)s * S2;
    float4 v[7];
#pragma unroll
    for (int i = 0; i < 7; i++) v[i] = *(const float4*)(p + 4 * i);
    float2 q = *(const float2*)(p + 28);
    float* o = hout + (size_t)d * S2;
#pragma unroll
    for (int i = 0; i < 7; i++)
        red4(o + 4 * i, c * v[i].x, c * v[i].y, c * v[i].z, c * v[i].w);
    red2(o + 28, c * q.x, c * q.y);
}

// ---------------- layer-1 node step: O1 += Tnew@Wk ; Dnext = -Tprev ---------
__global__ void k_l1_node(const float* __restrict__ Tnew, const float* __restrict__ Tprev,
                          float* __restrict__ Dnext, const float* __restrict__ Wk) {
    __shared__ float sW[FIN * HID];
    for (int i = threadIdx.x; i < FIN * HID; i += blockDim.x) sW[i] = Wk[i];
    __syncthreads();
    int n = blockIdx.x * blockDim.x + threadIdx.x;
    if (n >= NN) return;
    const float* tr = Tnew + (size_t)n * S1;
    float t[FIN];
#pragma unroll
    for (int i = 0; i < FIN; i++) t[i] = tr[i];
    float* o = g_O1 + (size_t)n * S2;
#pragma unroll
    for (int j = 0; j < HID; j++) {
        float acc = o[j];
#pragma unroll
        for (int i = 0; i < FIN; i++) acc += t[i] * sW[i * HID + j];
        o[j] = acc;
    }
    const float4* pp = (const float4*)(Tprev + (size_t)n * S1);
    float4* dd = (float4*)(Dnext + (size_t)n * S1);
#pragma unroll
    for (int i = 0; i < 3; i++) {
        float4 v = pp[i];
        dd[i] = make_float4(-v.x, -v.y, -v.z, -v.w);
    }
}

// -------- layer-1 final: h=relu(O1+T4@W1[4]+b1); A2=h, B2=0, O2=h@W2[0] -----
__global__ void k_l1_final(const float* __restrict__ Tnew,
                           const float* __restrict__ W14, const float* __restrict__ b1,
                           const float* __restrict__ W20) {
    __shared__ float sW4[FIN * HID];
    __shared__ float sW0[HID * HID];
    __shared__ float sb[HID];
    for (int i = threadIdx.x; i < FIN * HID; i += blockDim.x) sW4[i] = W14[i];
    for (int i = threadIdx.x; i < HID * HID; i += blockDim.x) sW0[i] = W20[i];
    for (int i = threadIdx.x; i < HID; i += blockDim.x) sb[i] = b1[i];
    __syncthreads();
    int n = blockIdx.x * blockDim.x + threadIdx.x;
    if (n >= NN) return;
    const float* tr = Tnew + (size_t)n * S1;
    float t[FIN];
#pragma unroll
    for (int i = 0; i < FIN; i++) t[i] = tr[i];
    float* o1 = g_O1 + (size_t)n * S2;
    float h[HID];
#pragma unroll
    for (int j = 0; j < HID; j++) {
        float acc = o1[j];
#pragma unroll
        for (int i = 0; i < FIN; i++) acc += t[i] * sW4[i * HID + j];
        h[j] = fmaxf(acc + sb[j], 0.f);
    }
    float* a2 = g_A2 + (size_t)n * S2;
#pragma unroll
    for (int j = 0; j < HID; j++) a2[j] = h[j];
    a2[30] = 0.f; a2[31] = 0.f;
    float4* b2 = (float4*)(g_B2 + (size_t)n * S2);
#pragma unroll
    for (int i = 0; i < 8; i++) b2[i] = make_float4(0.f, 0.f, 0.f, 0.f);
    float* o2 = g_O2 + (size_t)n * S2;
#pragma unroll
    for (int j = 0; j < HID; j++) {
        float acc = 0.f;
#pragma unroll
        for (int i = 0; i < HID; i++) acc += h[i] * sW0[i * HID + j];
        o2[j] = acc;
    }
}

// ---------------- layer-2 node step -----------------------------------------
__global__ void k_l2_node(const float* __restrict__ Tnew, const float* __restrict__ Tprev,
                          float* __restrict__ Dnext, const float* __restrict__ Wk) {
    __shared__ float sW[HID * HID];
    for (int i = threadIdx.x; i < HID * HID; i += blockDim.x) sW[i] = Wk[i];
    __syncthreads();
    int n = blockIdx.x * blockDim.x + threadIdx.x;
    if (n >= NN) return;
    const float* tr = Tnew + (size_t)n * S2;
    float t[HID];
#pragma unroll
    for (int i = 0; i < HID; i++) t[i] = tr[i];
    float* o = g_O2 + (size_t)n * S2;
#pragma unroll
    for (int j = 0; j < HID; j++) {
        float acc = o[j];
#pragma unroll
        for (int i = 0; i < HID; i++) acc += t[i] * sW[i * HID + j];
        o[j] = acc;
    }
    const float4* pp = (const float4*)(Tprev + (size_t)n * S2);
    float4* dd = (float4*)(Dnext + (size_t)n * S2);
#pragma unroll
    for (int i = 0; i < 8; i++) {
        float4 v = pp[i];
        dd[i] = make_float4(-v.x, -v.y, -v.z, -v.w);
    }
}

// -------- layer-2 final + head: out = relu(O2+T4@W2[4]+b2) @ Wl + bl --------
__global__ void k_l2_final(const float* __restrict__ Tnew,
                           const float* __restrict__ W24, const float* __restrict__ b2,
                           const float* __restrict__ Wl, const float* __restrict__ bl,
                           float* __restrict__ out) {
    __shared__ float sW4[HID * HID];
    __shared__ float sWl[HID * NCLS];
    __shared__ float sb2[HID];
    __shared__ float sbl[NCLS];
    for (int i = threadIdx.x; i < HID * HID; i += blockDim.x) sW4[i] = W24[i];
    for (int i = threadIdx.x; i < HID * NCLS; i += blockDim.x) sWl[i] = Wl[i];
    for (int i = threadIdx.x; i < HID; i += blockDim.x) sb2[i] = b2[i];
    for (int i = threadIdx.x; i < NCLS; i += blockDim.x) sbl[i] = bl[i];
    __syncthreads();
    int n = blockIdx.x * blockDim.x + threadIdx.x;
    if (n >= NN) return;
    const float* tr = Tnew + (size_t)n * S2;
    float t[HID];
#pragma unroll
    for (int i = 0; i < HID; i++) t[i] = tr[i];
    float* o2 = g_O2 + (size_t)n * S2;
    float h[HID];
#pragma unroll
    for (int j = 0; j < HID; j++) {
        float acc = o2[j];
#pragma unroll
        for (int i = 0; i < HID; i++) acc += t[i] * sW4[i * HID + j];
        h[j] = fmaxf(acc + sb2[j], 0.f);
    }
    float r[NCLS];
#pragma unroll
    for (int c = 0; c < NCLS; c++) {
        float acc = sbl[c];
#pragma unroll
        for (int j = 0; j < HID; j++) acc += h[j] * sWl[j * NCLS + c];
        r[c] = acc;
    }
    *(float4*)(out + (size_t)n * NCLS) = make_float4(r[0], r[1], r[2], r[3]);
}

// ---------------- launch -----------------------------------------------------
extern "C" void kernel_launch(void* const* d_in, const int* in_sizes, int n_in,
                              void* d_out, int out_size) {
    const float* x  = (const float*)d_in[0];
    const int*   ei = (const int*)d_in[1];
    const float* ew = (const float*)d_in[2];
    const float* W1 = (const float*)d_in[3];
    const float* b1 = (const float*)d_in[4];
    const float* W2 = (const float*)d_in[5];
    const float* b2 = (const float*)d_in[6];
    const float* Wl = (const float*)d_in[7];
    const float* bl = (const float*)d_in[8];
    float* out = (float*)d_out;

    const int* src = ei;
    const int* dst = ei + NE;

    float *T0, *T1, *T2, *A2, *B2, *C2;
    cudaGetSymbolAddress((void**)&T0, g_T0);
    cudaGetSymbolAddress((void**)&T1, g_T1);
    cudaGetSymbolAddress((void**)&T2, g_T2);
    cudaGetSymbolAddress((void**)&A2, g_A2);
    cudaGetSymbolAddress((void**)&B2, g_B2);
    cudaGetSymbolAddress((void**)&C2, g_C2);

    dim3 blk(256);
    dim3 ng((NN + 255) / 256);
    dim3 eg((NE + 255) / 256);

    // norm
    k_zero_deg<<<ng, blk>>>();
    k_deg<<<eg, blk>>>(src, dst, ew);
    k_norm<<<eg, blk>>>(src, dst, ew);

    // ---- layer 1 (dim 10, stride 12) ----
    k_l1_init<<<ng, blk>>>(x, W1 + 0 * FIN * HID);
    k_prop10<<<eg, blk>>>(T0, T1, src, dst, 1.0f);                 // T1 = S x
    k_l1_node<<<ng, blk>>>(T1, T0, T2, W1 + 1 * FIN * HID);        // O1+=T1@W1; T2=-T0
    k_prop10<<<eg, blk>>>(T1, T2, src, dst, 2.0f);                 // T2 = 2 S T1 - T0
    k_l1_node<<<ng, blk>>>(T2, T1, T0, W1 + 2 * FIN * HID);        // O1+=T2@W2; T0=-T1
    k_prop10<<<eg, blk>>>(T2, T0, src, dst, 2.0f);                 // T3
    k_l1_node<<<ng, blk>>>(T0, T2, T1, W1 + 3 * FIN * HID);        // O1+=T3@W3; T1=-T2
    k_prop10<<<eg, blk>>>(T0, T1, src, dst, 2.0f);                 // T4
    k_l1_final<<<ng, blk>>>(T1, W1 + 4 * FIN * HID, b1, W2 + 0 * HID * HID);

    // ---- layer 2 (dim 30, stride 32) ----
    k_prop30<<<eg, blk>>>(A2, B2, src, dst, 1.0f);                 // T1
    k_l2_node<<<ng, blk>>>(B2, A2, C2, W2 + 1 * HID * HID);
    k_prop30<<<eg, blk>>>(B2, C2, src, dst, 2.0f);                 // T2
    k_l2_node<<<ng, blk>>>(C2, B2, A2, W2 + 2 * HID * HID);
    k_prop30<<<eg, blk>>>(C2, A2, src, dst, 2.0f);                 // T3
    k_l2_node<<<ng, blk>>>(A2, C2, B2, W2 + 3 * HID * HID);
    k_prop30<<<eg, blk>>>(A2, B2, src, dst, 2.0f);                 // T4
    k_l2_final<<<ng, blk>>>(B2, W2 + 4 * HID * HID, b2, Wl, bl, out);
}

// round 5
// speedup vs baseline: 1.4332x; 1.4332x over previous
#include <cuda_runtime.h>
#include <cstddef>

#define NN   100000
#define NE   3200000
#define FIN  10
#define HID  30
#define NCLS 4
#define S1   16   // padded stride for layer-1 T buffers (10 -> 16 floats = 64B, power-of-2 groups)
#define S2   32   // padded stride for layer-2 / accumulator buffers (30 -> 32 floats = 128B)

// ---------------- scratch (static device globals; no runtime allocation) ----
__device__ __align__(16) float g_deg[NN];
__device__ __align__(16) float g_norm[NE];
__device__ __align__(16) float g_T0[NN * S1];
__device__ __align__(16) float g_T1[NN * S1];
__device__ __align__(16) float g_T2[NN * S1];
__device__ __align__(16) float g_A2[NN * S2];
__device__ __align__(16) float g_B2[NN * S2];
__device__ __align__(16) float g_C2[NN * S2];
__device__ __align__(16) float g_O1[NN * S2];
__device__ __align__(16) float g_O2[NN * S2];

// ---------------- vector reductions (sm_90+): no-return global float adds ---
__device__ __forceinline__ void red4(float* addr, float x, float y, float z, float w) {
    asm volatile("red.global.add.v4.f32 [%0], {%1,%2,%3,%4};"
                 :: "l"(addr), "f"(x), "f"(y), "f"(z), "f"(w) : "memory");
}

// ---------------- norm pipeline --------------------------------------------
__global__ void k_zero_deg() {
    int i = blockIdx.x * blockDim.x + threadIdx.x;
    if (i < NN) g_deg[i] = 0.f;
}

__global__ void k_deg(const int* __restrict__ src, const int* __restrict__ dst,
                      const float* __restrict__ w) {
    int e = blockIdx.x * blockDim.x + threadIdx.x;
    if (e >= NE) return;
    int s = src[e];
    if (s != dst[e]) atomicAdd(&g_deg[s], w[e]);
}

__global__ void k_norm(const int* __restrict__ src, const int* __restrict__ dst,
                       const float* __restrict__ w) {
    int e = blockIdx.x * blockDim.x + threadIdx.x;
    if (e >= NE) return;
    int s = src[e], d = dst[e];
    float we = (s == d) ? 0.f : w[e];
    float ds = g_deg[s], dd = g_deg[d];
    float is = (ds > 0.f) ? rsqrtf(ds) : 0.f;
    float id = (dd > 0.f) ? rsqrtf(dd) : 0.f;
    g_norm[e] = -is * we * id;
}

// ---------------- layer 1 init: T0 = pad(x), T1 = 0, O1 = x @ W1[0] ---------
__global__ void k_l1_init(const float* __restrict__ x, const float* __restrict__ W0) {
    __shared__ float sW[FIN * HID];
    for (int i = threadIdx.x; i < FIN * HID; i += blockDim.x) sW[i] = W0[i];
    __syncthreads();
    int n = blockIdx.x * blockDim.x + threadIdx.x;
    if (n >= NN) return;
    float t[FIN];
    const float* xr = x + (size_t)n * FIN;
#pragma unroll
    for (int i = 0; i < FIN; i++) t[i] = xr[i];
    float* a = g_T0 + (size_t)n * S1;
#pragma unroll
    for (int i = 0; i < FIN; i++) a[i] = t[i];
#pragma unroll
    for (int i = FIN; i < S1; i++) a[i] = 0.f;
    float4* b = (float4*)(g_T1 + (size_t)n * S1);
#pragma unroll
    for (int i = 0; i < S1 / 4; i++) b[i] = make_float4(0.f, 0.f, 0.f, 0.f);
    float* o = g_O1 + (size_t)n * S2;
#pragma unroll
    for (int j = 0; j < HID; j++) {
        float acc = 0.f;
#pragma unroll
        for (int i = 0; i < FIN; i++) acc += t[i] * sW[i * HID + j];
        o[j] = acc;
    }
}

// ---------------- cooperative scatter props ---------------------------------
// 4 lanes per edge; lane off=0..3 handles float4 slot off of the 16-float row.
// off==3 is padding-only -> predicated off. One LDG.128 touches 8 rows (<=8
// lines) instead of 32; same for the red.
__global__ void k_prop10(const float* __restrict__ hin, float* __restrict__ hout,
                         const int* __restrict__ src, const int* __restrict__ dst,
                         float scale) {
    int t = blockIdx.x * blockDim.x + threadIdx.x;
    int e   = t >> 2;
    int off = t & 3;
    if (e >= NE || off == 3) return;
    float c = g_norm[e] * scale;
    if (c == 0.f) return;
    int s = src[e], d = dst[e];
    float4 v = *(const float4*)(hin + ((size_t)s << 4) + (off << 2));
    red4(hout + ((size_t)d << 4) + (off << 2), c * v.x, c * v.y, c * v.z, c * v.w);
}

// 8 lanes per edge; lane off=0..7 handles float4 slot off of the 32-float row.
// One LDG.128 covers 4 full rows (4 lines) instead of 32.
__global__ void k_prop30(const float* __restrict__ hin, float* __restrict__ hout,
                         const int* __restrict__ src, const int* __restrict__ dst,
                         float scale) {
    int t = blockIdx.x * blockDim.x + threadIdx.x;
    int e   = t >> 3;
    int off = t & 7;
    if (e >= NE) return;
    float c = g_norm[e] * scale;
    if (c == 0.f) return;
    int s = src[e], d = dst[e];
    float4 v = *(const float4*)(hin + ((size_t)s << 5) + (off << 2));
    red4(hout + ((size_t)d << 5) + (off << 2), c * v.x, c * v.y, c * v.z, c * v.w);
}

// ---------------- layer-1 node step: O1 += Tnew@Wk ; Dnext = -Tprev ---------
__global__ void k_l1_node(const float* __restrict__ Tnew, const float* __restrict__ Tprev,
                          float* __restrict__ Dnext, const float* __restrict__ Wk) {
    __shared__ float sW[FIN * HID];
    for (int i = threadIdx.x; i < FIN * HID; i += blockDim.x) sW[i] = Wk[i];
    __syncthreads();
    int n = blockIdx.x * blockDim.x + threadIdx.x;
    if (n >= NN) return;
    const float* tr = Tnew + (size_t)n * S1;
    float t[FIN];
#pragma unroll
    for (int i = 0; i < FIN; i++) t[i] = tr[i];
    float* o = g_O1 + (size_t)n * S2;
#pragma unroll
    for (int j = 0; j < HID; j++) {
        float acc = o[j];
#pragma unroll
        for (int i = 0; i < FIN; i++) acc += t[i] * sW[i * HID + j];
        o[j] = acc;
    }
    const float4* pp = (const float4*)(Tprev + (size_t)n * S1);
    float4* dd = (float4*)(Dnext + (size_t)n * S1);
#pragma unroll
    for (int i = 0; i < S1 / 4; i++) {
        float4 v = pp[i];
        dd[i] = make_float4(-v.x, -v.y, -v.z, -v.w);
    }
}

// -------- layer-1 final: h=relu(O1+T4@W1[4]+b1); A2=h, B2=0, O2=h@W2[0] -----
__global__ void k_l1_final(const float* __restrict__ Tnew,
                           const float* __restrict__ W14, const float* __restrict__ b1,
                           const float* __restrict__ W20) {
    __shared__ float sW4[FIN * HID];
    __shared__ float sW0[HID * HID];
    __shared__ float sb[HID];
    for (int i = threadIdx.x; i < FIN * HID; i += blockDim.x) sW4[i] = W14[i];
    for (int i = threadIdx.x; i < HID * HID; i += blockDim.x) sW0[i] = W20[i];
    for (int i = threadIdx.x; i < HID; i += blockDim.x) sb[i] = b1[i];
    __syncthreads();
    int n = blockIdx.x * blockDim.x + threadIdx.x;
    if (n >= NN) return;
    const float* tr = Tnew + (size_t)n * S1;
    float t[FIN];
#pragma unroll
    for (int i = 0; i < FIN; i++) t[i] = tr[i];
    float* o1 = g_O1 + (size_t)n * S2;
    float h[HID];
#pragma unroll
    for (int j = 0; j < HID; j++) {
        float acc = o1[j];
#pragma unroll
        for (int i = 0; i < FIN; i++) acc += t[i] * sW4[i * HID + j];
        h[j] = fmaxf(acc + sb[j], 0.f);
    }
    float* a2 = g_A2 + (size_t)n * S2;
#pragma unroll
    for (int j = 0; j < HID; j++) a2[j] = h[j];
    a2[30] = 0.f; a2[31] = 0.f;
    float4* b2 = (float4*)(g_B2 + (size_t)n * S2);
#pragma unroll
    for (int i = 0; i < 8; i++) b2[i] = make_float4(0.f, 0.f, 0.f, 0.f);
    float* o2 = g_O2 + (size_t)n * S2;
#pragma unroll
    for (int j = 0; j < HID; j++) {
        float acc = 0.f;
#pragma unroll
        for (int i = 0; i < HID; i++) acc += h[i] * sW0[i * HID + j];
        o2[j] = acc;
    }
}

// ---------------- layer-2 node step -----------------------------------------
__global__ void k_l2_node(const float* __restrict__ Tnew, const float* __restrict__ Tprev,
                          float* __restrict__ Dnext, const float* __restrict__ Wk) {
    __shared__ float sW[HID * HID];
    for (int i = threadIdx.x; i < HID * HID; i += blockDim.x) sW[i] = Wk[i];
    __syncthreads();
    int n = blockIdx.x * blockDim.x + threadIdx.x;
    if (n >= NN) return;
    const float* tr = Tnew + (size_t)n * S2;
    float t[HID];
#pragma unroll
    for (int i = 0; i < HID; i++) t[i] = tr[i];
    float* o = g_O2 + (size_t)n * S2;
#pragma unroll
    for (int j = 0; j < HID; j++) {
        float acc = o[j];
#pragma unroll
        for (int i = 0; i < HID; i++) acc += t[i] * sW[i * HID + j];
        o[j] = acc;
    }
    const float4* pp = (const float4*)(Tprev + (size_t)n * S2);
    float4* dd = (float4*)(Dnext + (size_t)n * S2);
#pragma unroll
    for (int i = 0; i < 8; i++) {
        float4 v = pp[i];
        dd[i] = make_float4(-v.x, -v.y, -v.z, -v.w);
    }
}

// -------- layer-2 final + head: out = relu(O2+T4@W2[4]+b2) @ Wl + bl --------
__global__ void k_l2_final(const float* __restrict__ Tnew,
                           const float* __restrict__ W24, const float* __restrict__ b2,
                           const float* __restrict__ Wl, const float* __restrict__ bl,
                           float* __restrict__ out) {
    __shared__ float sW4[HID * HID];
    __shared__ float sWl[HID * NCLS];
    __shared__ float sb2[HID];
    __shared__ float sbl[NCLS];
    for (int i = threadIdx.x; i < HID * HID; i += blockDim.x) sW4[i] = W24[i];
    for (int i = threadIdx.x; i < HID * NCLS; i += blockDim.x) sWl[i] = Wl[i];
    for (int i = threadIdx.x; i < HID; i += blockDim.x) sb2[i] = b2[i];
    for (int i = threadIdx.x; i < NCLS; i += blockDim.x) sbl[i] = bl[i];
    __syncthreads();
    int n = blockIdx.x * blockDim.x + threadIdx.x;
    if (n >= NN) return;
    const float* tr = Tnew + (size_t)n * S2;
    float t[HID];
#pragma unroll
    for (int i = 0; i < HID; i++) t[i] = tr[i];
    float* o2 = g_O2 + (size_t)n * S2;
    float h[HID];
#pragma unroll
    for (int j = 0; j < HID; j++) {
        float acc = o2[j];
#pragma unroll
        for (int i = 0; i < HID; i++) acc += t[i] * sW4[i * HID + j];
        h[j] = fmaxf(acc + sb2[j], 0.f);
    }
    float r[NCLS];
#pragma unroll
    for (int c = 0; c < NCLS; c++) {
        float acc = sbl[c];
#pragma unroll
        for (int j = 0; j < HID; j++) acc += h[j] * sWl[j * NCLS + c];
        r[c] = acc;
    }
    *(float4*)(out + (size_t)n * NCLS) = make_float4(r[0], r[1], r[2], r[3]);
}

// ---------------- launch -----------------------------------------------------
extern "C" void kernel_launch(void* const* d_in, const int* in_sizes, int n_in,
                              void* d_out, int out_size) {
    const float* x  = (const float*)d_in[0];
    const int*   ei = (const int*)d_in[1];
    const float* ew = (const float*)d_in[2];
    const float* W1 = (const float*)d_in[3];
    const float* b1 = (const float*)d_in[4];
    const float* W2 = (const float*)d_in[5];
    const float* b2 = (const float*)d_in[6];
    const float* Wl = (const float*)d_in[7];
    const float* bl = (const float*)d_in[8];
    float* out = (float*)d_out;

    const int* src = ei;
    const int* dst = ei + NE;

    float *T0, *T1, *T2, *A2, *B2, *C2;
    cudaGetSymbolAddress((void**)&T0, g_T0);
    cudaGetSymbolAddress((void**)&T1, g_T1);
    cudaGetSymbolAddress((void**)&T2, g_T2);
    cudaGetSymbolAddress((void**)&A2, g_A2);
    cudaGetSymbolAddress((void**)&B2, g_B2);
    cudaGetSymbolAddress((void**)&C2, g_C2);

    dim3 blk(256);
    dim3 ng((NN + 255) / 256);
    dim3 eg((NE + 255) / 256);
    // cooperative prop grids: 4 threads/edge (layer1), 8 threads/edge (layer2)
    dim3 eg4((NE * 4 + 255) / 256);
    dim3 eg8((NE * 8 + 255) / 256);

    // norm
    k_zero_deg<<<ng, blk>>>();
    k_deg<<<eg, blk>>>(src, dst, ew);
    k_norm<<<eg, blk>>>(src, dst, ew);

    // ---- layer 1 (dim 10, stride 16) ----
    k_l1_init<<<ng, blk>>>(x, W1 + 0 * FIN * HID);
    k_prop10<<<eg4, blk>>>(T0, T1, src, dst, 1.0f);                // T1 = S x
    k_l1_node<<<ng, blk>>>(T1, T0, T2, W1 + 1 * FIN * HID);        // O1+=T1@W1; T2=-T0
    k_prop10<<<eg4, blk>>>(T1, T2, src, dst, 2.0f);                // T2 = 2 S T1 - T0
    k_l1_node<<<ng, blk>>>(T2, T1, T0, W1 + 2 * FIN * HID);        // O1+=T2@W2; T0=-T1
    k_prop10<<<eg4, blk>>>(T2, T0, src, dst, 2.0f);                // T3
    k_l1_node<<<ng, blk>>>(T0, T2, T1, W1 + 3 * FIN * HID);        // O1+=T3@W3; T1=-T2
    k_prop10<<<eg4, blk>>>(T0, T1, src, dst, 2.0f);                // T4
    k_l1_final<<<ng, blk>>>(T1, W1 + 4 * FIN * HID, b1, W2 + 0 * HID * HID);

    // ---- layer 2 (dim 30, stride 32) ----
    k_prop30<<<eg8, blk>>>(A2, B2, src, dst, 1.0f);                // T1
    k_l2_node<<<ng, blk>>>(B2, A2, C2, W2 + 1 * HID * HID);
    k_prop30<<<eg8, blk>>>(B2, C2, src, dst, 2.0f);                // T2
    k_l2_node<<<ng, blk>>>(C2, B2, A2, W2 + 2 * HID * HID);
    k_prop30<<<eg8, blk>>>(C2, A2, src, dst, 2.0f);                // T3
    k_l2_node<<<ng, blk>>>(A2, C2, B2, W2 + 3 * HID * HID);
    k_prop30<<<eg8, blk>>>(A2, B2, src, dst, 2.0f);                // T4
    k_l2_final<<<ng, blk>>>(B2, W2 + 4 * HID * HID, b2, Wl, bl, out);
}

// round 6
// speedup vs baseline: 2.4595x; 1.7160x over previous
#include <cuda_runtime.h>
#include <cstddef>

#define NN   100000
#define NE   3200000
#define FIN  10
#define HID  30
#define NCLS 4
#define S1   16   // layer-1 row stride (floats): 10 -> 16 (64B)
#define S2   32   // layer-2 row stride (floats): 30 -> 32 (128B)

#define SCAN_BS 512
#define SCAN_NB ((NN + SCAN_BS - 1) / SCAN_BS)   // 196

// ---------------- scratch (static device globals) ---------------------------
__device__ __align__(16) float g_deg[NN];
__device__ __align__(16) float g_norm[NE];
__device__ __align__(16) int   g_cnt[NN];
__device__ __align__(16) int   g_rs[NN + 1];     // CSR row starts (by dst)
__device__ __align__(16) int   g_cur[NN];        // scatter cursors
__device__ __align__(16) int   g_bsum[SCAN_NB];
__device__ __align__(16) int   g_boff[SCAN_NB];
__device__ __align__(16) int2  g_recs[NE];       // {src, norm(float bits)} sorted by dst
__device__ __align__(16) float g_T0[NN * S1];
__device__ __align__(16) float g_T1[NN * S1];
__device__ __align__(16) float g_T2[NN * S1];
__device__ __align__(16) float g_A2[NN * S2];
__device__ __align__(16) float g_B2[NN * S2];
__device__ __align__(16) float g_C2[NN * S2];
__device__ __align__(16) float g_O1[NN * S2];
__device__ __align__(16) float g_O2[NN * S2];

// ---------------- norm pipeline ---------------------------------------------
__global__ void k_zero() {
    int i = blockIdx.x * blockDim.x + threadIdx.x;
    if (i < NN) { g_deg[i] = 0.f; g_cnt[i] = 0; }
}

__global__ void k_deg(const int* __restrict__ src, const int* __restrict__ dst,
                      const float* __restrict__ w) {
    int e = blockIdx.x * blockDim.x + threadIdx.x;
    if (e >= NE) return;
    int s = src[e];
    if (s != dst[e]) atomicAdd(&g_deg[s], w[e]);
}

__global__ void k_norm(const int* __restrict__ src, const int* __restrict__ dst,
                       const float* __restrict__ w) {
    int e = blockIdx.x * blockDim.x + threadIdx.x;
    if (e >= NE) return;
    int s = src[e], d = dst[e];
    float we = (s == d) ? 0.f : w[e];
    float ds = g_deg[s], dd = g_deg[d];
    float is = (ds > 0.f) ? rsqrtf(ds) : 0.f;
    float id = (dd > 0.f) ? rsqrtf(dd) : 0.f;
    g_norm[e] = -is * we * id;
    atomicAdd(&g_cnt[d], 1);   // histogram for CSR (all edges kept; norm 0 adds 0)
}

// ---------------- CSR build: 2-level exclusive scan + scatter ----------------
__global__ void k_scan1() {
    __shared__ int sh[SCAN_BS];
    int tid = threadIdx.x;
    int i = blockIdx.x * SCAN_BS + tid;
    int v = (i < NN) ? g_cnt[i] : 0;
    sh[tid] = v;
    __syncthreads();
#pragma unroll
    for (int ofs = 1; ofs < SCAN_BS; ofs <<= 1) {
        int t = (tid >= ofs) ? sh[tid - ofs] : 0;
        __syncthreads();
        sh[tid] += t;
        __syncthreads();
    }
    if (i < NN) g_rs[i] = sh[tid] - v;           // exclusive
    if (tid == SCAN_BS - 1) g_bsum[blockIdx.x] = sh[tid];
}

__global__ void k_scan2() {
    __shared__ int sh[256];
    int tid = threadIdx.x;
    int v = (tid < SCAN_NB) ? g_bsum[tid] : 0;
    sh[tid] = v;
    __syncthreads();
#pragma unroll
    for (int ofs = 1; ofs < 256; ofs <<= 1) {
        int t = (tid >= ofs) ? sh[tid - ofs] : 0;
        __syncthreads();
        sh[tid] += t;
        __syncthreads();
    }
    if (tid < SCAN_NB) g_boff[tid] = sh[tid] - v;  // exclusive
}

__global__ void k_scan3() {
    int i = blockIdx.x * blockDim.x + threadIdx.x;
    if (i < NN) {
        int r = g_rs[i] + g_boff[i / SCAN_BS];
        g_rs[i] = r;
        g_cur[i] = r;
    }
    if (i == 0) g_rs[NN] = NE;
}

__global__ void k_build(const int* __restrict__ src, const int* __restrict__ dst) {
    int e = blockIdx.x * blockDim.x + threadIdx.x;
    if (e >= NE) return;
    int d = dst[e];
    int p = atomicAdd(&g_cur[d], 1);
    g_recs[p] = make_int2(src[e], __float_as_int(g_norm[e]));
}

// ---------------- layer 1 init: T0 = pad(x), O1 = x @ W1[0] ------------------
__global__ void k_l1_init(const float* __restrict__ x, const float* __restrict__ W0) {
    __shared__ float sW[FIN * HID];
    for (int i = threadIdx.x; i < FIN * HID; i += blockDim.x) sW[i] = W0[i];
    __syncthreads();
    int n = blockIdx.x * blockDim.x + threadIdx.x;
    if (n >= NN) return;
    float t[FIN];
    const float* xr = x + (size_t)n * FIN;
#pragma unroll
    for (int i = 0; i < FIN; i++) t[i] = xr[i];
    float* a = g_T0 + (size_t)n * S1;
#pragma unroll
    for (int i = 0; i < FIN; i++) a[i] = t[i];
#pragma unroll
    for (int i = FIN; i < S1; i++) a[i] = 0.f;
    float* o = g_O1 + (size_t)n * S2;
#pragma unroll
    for (int j = 0; j < HID; j++) {
        float acc = 0.f;
#pragma unroll
        for (int i = 0; i < FIN; i++) acc += t[i] * sW[i * HID + j];
        o[j] = acc;
    }
}

// ---------------- CSR gather props -------------------------------------------
// hout[n] = (Tprev ? -Tprev[n] : 0) + sum_{e in in(n)} scale*norm_e * hin[src_e]
// 4 lanes per node (16-float rows). Unrolled x2 for gather MLP.
__global__ void k_prop10(const float* __restrict__ hin, const float* __restrict__ Tprev,
                         float* __restrict__ hout, float scale) {
    int t = blockIdx.x * blockDim.x + threadIdx.x;
    int n = t >> 2, off = t & 3;
    if (n >= NN) return;
    int s = g_rs[n], e = g_rs[n + 1];
    float4 acc = make_float4(0.f, 0.f, 0.f, 0.f);
    if (Tprev) {
        float4 v = *(const float4*)(Tprev + ((size_t)n << 4) + (off << 2));
        acc = make_float4(-v.x, -v.y, -v.z, -v.w);
    }
    int i = s;
    for (; i + 1 < e; i += 2) {
        int2 r0 = g_recs[i], r1 = g_recs[i + 1];
        float c0 = __int_as_float(r0.y) * scale;
        float c1 = __int_as_float(r1.y) * scale;
        float4 v0 = *(const float4*)(hin + ((size_t)r0.x << 4) + (off << 2));
        float4 v1 = *(const float4*)(hin + ((size_t)r1.x << 4) + (off << 2));
        acc.x += c0 * v0.x + c1 * v1.x;
        acc.y += c0 * v0.y + c1 * v1.y;
        acc.z += c0 * v0.z + c1 * v1.z;
        acc.w += c0 * v0.w + c1 * v1.w;
    }
    if (i < e) {
        int2 r = g_recs[i];
        float c = __int_as_float(r.y) * scale;
        float4 v = *(const float4*)(hin + ((size_t)r.x << 4) + (off << 2));
        acc.x += c * v.x; acc.y += c * v.y; acc.z += c * v.z; acc.w += c * v.w;
    }
    *(float4*)(hout + ((size_t)n << 4) + (off << 2)) = acc;
}

// 8 lanes per node (32-float rows).
__global__ void k_prop30(const float* __restrict__ hin, const float* __restrict__ Tprev,
                         float* __restrict__ hout, float scale) {
    int t = blockIdx.x * blockDim.x + threadIdx.x;
    int n = t >> 3, off = t & 7;
    if (n >= NN) return;
    int s = g_rs[n], e = g_rs[n + 1];
    float4 acc = make_float4(0.f, 0.f, 0.f, 0.f);
    if (Tprev) {
        float4 v = *(const float4*)(Tprev + ((size_t)n << 5) + (off << 2));
        acc = make_float4(-v.x, -v.y, -v.z, -v.w);
    }
    int i = s;
    for (; i + 1 < e; i += 2) {
        int2 r0 = g_recs[i], r1 = g_recs[i + 1];
        float c0 = __int_as_float(r0.y) * scale;
        float c1 = __int_as_float(r1.y) * scale;
        float4 v0 = *(const float4*)(hin + ((size_t)r0.x << 5) + (off << 2));
        float4 v1 = *(const float4*)(hin + ((size_t)r1.x << 5) + (off << 2));
        acc.x += c0 * v0.x + c1 * v1.x;
        acc.y += c0 * v0.y + c1 * v1.y;
        acc.z += c0 * v0.z + c1 * v1.z;
        acc.w += c0 * v0.w + c1 * v1.w;
    }
    if (i < e) {
        int2 r = g_recs[i];
        float c = __int_as_float(r.y) * scale;
        float4 v = *(const float4*)(hin + ((size_t)r.x << 5) + (off << 2));
        acc.x += c * v.x; acc.y += c * v.y; acc.z += c * v.z; acc.w += c * v.w;
    }
    *(float4*)(hout + ((size_t)n << 5) + (off << 2)) = acc;
}

// ---------------- node matvec steps (accumulate only) ------------------------
__global__ void k_l1_node(const float* __restrict__ Tnew, const float* __restrict__ Wk) {
    __shared__ float sW[FIN * HID];
    for (int i = threadIdx.x; i < FIN * HID; i += blockDim.x) sW[i] = Wk[i];
    __syncthreads();
    int n = blockIdx.x * blockDim.x + threadIdx.x;
    if (n >= NN) return;
    const float* tr = Tnew + (size_t)n * S1;
    float t[FIN];
#pragma unroll
    for (int i = 0; i < FIN; i++) t[i] = tr[i];
    float* o = g_O1 + (size_t)n * S2;
#pragma unroll
    for (int j = 0; j < HID; j++) {
        float acc = o[j];
#pragma unroll
        for (int i = 0; i < FIN; i++) acc += t[i] * sW[i * HID + j];
        o[j] = acc;
    }
}

__global__ void k_l2_node(const float* __restrict__ Tnew, const float* __restrict__ Wk) {
    __shared__ float sW[HID * HID];
    for (int i = threadIdx.x; i < HID * HID; i += blockDim.x) sW[i] = Wk[i];
    __syncthreads();
    int n = blockIdx.x * blockDim.x + threadIdx.x;
    if (n >= NN) return;
    const float* tr = Tnew + (size_t)n * S2;
    float t[HID];
#pragma unroll
    for (int i = 0; i < HID; i++) t[i] = tr[i];
    float* o = g_O2 + (size_t)n * S2;
#pragma unroll
    for (int j = 0; j < HID; j++) {
        float acc = o[j];
#pragma unroll
        for (int i = 0; i < HID; i++) acc += t[i] * sW[i * HID + j];
        o[j] = acc;
    }
}

// -------- layer-1 final: h=relu(O1+T4@W1[4]+b1); A2=h (pads 0), O2=h@W2[0] ---
__global__ void k_l1_final(const float* __restrict__ Tnew,
                           const float* __restrict__ W14, const float* __restrict__ b1,
                           const float* __restrict__ W20) {
    __shared__ float sW4[FIN * HID];
    __shared__ float sW0[HID * HID];
    __shared__ float sb[HID];
    for (int i = threadIdx.x; i < FIN * HID; i += blockDim.x) sW4[i] = W14[i];
    for (int i = threadIdx.x; i < HID * HID; i += blockDim.x) sW0[i] = W20[i];
    for (int i = threadIdx.x; i < HID; i += blockDim.x) sb[i] = b1[i];
    __syncthreads();
    int n = blockIdx.x * blockDim.x + threadIdx.x;
    if (n >= NN) return;
    const float* tr = Tnew + (size_t)n * S1;
    float t[FIN];
#pragma unroll
    for (int i = 0; i < FIN; i++) t[i] = tr[i];
    float* o1 = g_O1 + (size_t)n * S2;
    float h[HID];
#pragma unroll
    for (int j = 0; j < HID; j++) {
        float acc = o1[j];
#pragma unroll
        for (int i = 0; i < FIN; i++) acc += t[i] * sW4[i * HID + j];
        h[j] = fmaxf(acc + sb[j], 0.f);
    }
    float* a2 = g_A2 + (size_t)n * S2;
#pragma unroll
    for (int j = 0; j < HID; j++) a2[j] = h[j];
    a2[30] = 0.f; a2[31] = 0.f;
    float* o2 = g_O2 + (size_t)n * S2;
#pragma unroll
    for (int j = 0; j < HID; j++) {
        float acc = 0.f;
#pragma unroll
        for (int i = 0; i < HID; i++) acc += h[i] * sW0[i * HID + j];
        o2[j] = acc;
    }
}

// -------- layer-2 final + head: out = relu(O2+T4@W2[4]+b2) @ Wl + bl ---------
__global__ void k_l2_final(const float* __restrict__ Tnew,
                           const float* __restrict__ W24, const float* __restrict__ b2,
                           const float* __restrict__ Wl, const float* __restrict__ bl,
                           float* __restrict__ out) {
    __shared__ float sW4[HID * HID];
    __shared__ float sWl[HID * NCLS];
    __shared__ float sb2[HID];
    __shared__ float sbl[NCLS];
    for (int i = threadIdx.x; i < HID * HID; i += blockDim.x) sW4[i] = W24[i];
    for (int i = threadIdx.x; i < HID * NCLS; i += blockDim.x) sWl[i] = Wl[i];
    for (int i = threadIdx.x; i < HID; i += blockDim.x) sb2[i] = b2[i];
    for (int i = threadIdx.x; i < NCLS; i += blockDim.x) sbl[i] = bl[i];
    __syncthreads();
    int n = blockIdx.x * blockDim.x + threadIdx.x;
    if (n >= NN) return;
    const float* tr = Tnew + (size_t)n * S2;
    float t[HID];
#pragma unroll
    for (int i = 0; i < HID; i++) t[i] = tr[i];
    float* o2 = g_O2 + (size_t)n * S2;
    float h[HID];
#pragma unroll
    for (int j = 0; j < HID; j++) {
        float acc = o2[j];
#pragma unroll
        for (int i = 0; i < HID; i++) acc += t[i] * sW4[i * HID + j];
        h[j] = fmaxf(acc + sb2[j], 0.f);
    }
    float r[NCLS];
#pragma unroll
    for (int c = 0; c < NCLS; c++) {
        float acc = sbl[c];
#pragma unroll
        for (int j = 0; j < HID; j++) acc += h[j] * sWl[j * NCLS + c];
        r[c] = acc;
    }
    *(float4*)(out + (size_t)n * NCLS) = make_float4(r[0], r[1], r[2], r[3]);
}

// ---------------- launch -----------------------------------------------------
extern "C" void kernel_launch(void* const* d_in, const int* in_sizes, int n_in,
                              void* d_out, int out_size) {
    const float* x  = (const float*)d_in[0];
    const int*   ei = (const int*)d_in[1];
    const float* ew = (const float*)d_in[2];
    const float* W1 = (const float*)d_in[3];
    const float* b1 = (const float*)d_in[4];
    const float* W2 = (const float*)d_in[5];
    const float* b2 = (const float*)d_in[6];
    const float* Wl = (const float*)d_in[7];
    const float* bl = (const float*)d_in[8];
    float* out = (float*)d_out;

    const int* src = ei;
    const int* dst = ei + NE;

    float *T0, *T1, *T2, *A2, *B2, *C2;
    cudaGetSymbolAddress((void**)&T0, g_T0);
    cudaGetSymbolAddress((void**)&T1, g_T1);
    cudaGetSymbolAddress((void**)&T2, g_T2);
    cudaGetSymbolAddress((void**)&A2, g_A2);
    cudaGetSymbolAddress((void**)&B2, g_B2);
    cudaGetSymbolAddress((void**)&C2, g_C2);

    dim3 blk(256);
    dim3 ng((NN + 255) / 256);
    dim3 eg((NE + 255) / 256);
    dim3 ng4((NN * 4 + 255) / 256);   // prop10: 4 lanes/node
    dim3 ng8((NN * 8 + 255) / 256);   // prop30: 8 lanes/node

    // norm + CSR build
    k_zero<<<ng, blk>>>();
    k_deg<<<eg, blk>>>(src, dst, ew);
    k_norm<<<eg, blk>>>(src, dst, ew);
    k_scan1<<<SCAN_NB, SCAN_BS>>>();
    k_scan2<<<1, 256>>>();
    k_scan3<<<ng, blk>>>();
    k_build<<<eg, blk>>>(src, dst);

    // ---- layer 1 (dim 10, stride 16) ----
    k_l1_init<<<ng, blk>>>(x, W1 + 0 * FIN * HID);
    k_prop10<<<ng4, blk>>>(T0, nullptr, T1, 1.0f);            // T1 = S T0
    k_l1_node<<<ng, blk>>>(T1, W1 + 1 * FIN * HID);
    k_prop10<<<ng4, blk>>>(T1, T0, T2, 2.0f);                 // T2 = 2S T1 - T0
    k_l1_node<<<ng, blk>>>(T2, W1 + 2 * FIN * HID);
    k_prop10<<<ng4, blk>>>(T2, T1, T0, 2.0f);                 // T3 (into T0)
    k_l1_node<<<ng, blk>>>(T0, W1 + 3 * FIN * HID);
    k_prop10<<<ng4, blk>>>(T0, T2, T1, 2.0f);                 // T4 (into T1)
    k_l1_final<<<ng, blk>>>(T1, W1 + 4 * FIN * HID, b1, W2 + 0 * HID * HID);

    // ---- layer 2 (dim 30, stride 32) ----
    k_prop30<<<ng8, blk>>>(A2, nullptr, B2, 1.0f);            // T1
    k_l2_node<<<ng, blk>>>(B2, W2 + 1 * HID * HID);
    k_prop30<<<ng8, blk>>>(B2, A2, C2, 2.0f);                 // T2
    k_l2_node<<<ng, blk>>>(C2, W2 + 2 * HID * HID);
    k_prop30<<<ng8, blk>>>(C2, B2, A2, 2.0f);                 // T3 (into A2)
    k_l2_node<<<ng, blk>>>(A2, W2 + 3 * HID * HID);
    k_prop30<<<ng8, blk>>>(A2, C2, B2, 2.0f);                 // T4 (into B2)
    k_l2_final<<<ng, blk>>>(B2, W2 + 4 * HID * HID, b2, Wl, bl, out);
}

// round 7
// speedup vs baseline: 2.4976x; 1.0155x over previous
#include <cuda_runtime.h>
#include <cstddef>

#define NN   100000
#define NE   3200000
#define FIN  10
#define HID  30
#define NCLS 4
#define S1   16   // layer-1 row stride (floats): 10 -> 16 (64B)
#define S2   32   // layer-2 row stride (floats): 30 -> 32 (128B)

#define SCAN_BS 512
#define SCAN_NB ((NN + SCAN_BS - 1) / SCAN_BS)   // 196

// ---------------- scratch (static device globals) ---------------------------
__device__ __align__(16) float g_deg[NN];
__device__ __align__(16) int   g_cnt[NN];
__device__ __align__(16) int   g_rs[NN + 1];     // CSR row starts (by dst)
__device__ __align__(16) int   g_cur[NN];        // scatter cursors
__device__ __align__(16) int   g_bsum[SCAN_NB];
__device__ __align__(16) int   g_boff[SCAN_NB];
__device__ __align__(16) int2  g_recs[NE];       // {src, norm bits} sorted by dst
__device__ __align__(16) float g_T0[NN * S1];
__device__ __align__(16) float g_T1[NN * S1];
__device__ __align__(16) float g_T2[NN * S1];
__device__ __align__(16) float g_A2[NN * S2];
__device__ __align__(16) float g_B2[NN * S2];
__device__ __align__(16) float g_C2[NN * S2];
__device__ __align__(16) float g_O1[NN * S2];
__device__ __align__(16) float g_O2[NN * S2];

// ---------------- degree + histogram -----------------------------------------
__global__ void k_zero() {
    int i = blockIdx.x * blockDim.x + threadIdx.x;
    if (i < NN) { g_deg[i] = 0.f; g_cnt[i] = 0; }
}

__global__ void k_deg(const int* __restrict__ src, const int* __restrict__ dst,
                      const float* __restrict__ w) {
    int e = blockIdx.x * blockDim.x + threadIdx.x;
    if (e >= NE) return;
    int s = src[e], d = dst[e];
    if (s != d) atomicAdd(&g_deg[s], w[e]);
    atomicAdd(&g_cnt[d], 1);           // histogram over ALL edges (recs hold NE entries)
}

// ---------------- CSR build: 2-level exclusive scan --------------------------
__global__ void k_scan1() {
    __shared__ int sh[SCAN_BS];
    int tid = threadIdx.x;
    int i = blockIdx.x * SCAN_BS + tid;
    int v = (i < NN) ? g_cnt[i] : 0;
    sh[tid] = v;
    __syncthreads();
#pragma unroll
    for (int ofs = 1; ofs < SCAN_BS; ofs <<= 1) {
        int t = (tid >= ofs) ? sh[tid - ofs] : 0;
        __syncthreads();
        sh[tid] += t;
        __syncthreads();
    }
    if (i < NN) g_rs[i] = sh[tid] - v;            // exclusive
    if (tid == SCAN_BS - 1) g_bsum[blockIdx.x] = sh[tid];
}

__global__ void k_scan2() {
    __shared__ int sh[256];
    int tid = threadIdx.x;
    int v = (tid < SCAN_NB) ? g_bsum[tid] : 0;
    sh[tid] = v;
    __syncthreads();
#pragma unroll
    for (int ofs = 1; ofs < 256; ofs <<= 1) {
        int t = (tid >= ofs) ? sh[tid - ofs] : 0;
        __syncthreads();
        sh[tid] += t;
        __syncthreads();
    }
    if (tid < SCAN_NB) g_boff[tid] = sh[tid] - v; // exclusive
}

__global__ void k_scan3() {
    int i = blockIdx.x * blockDim.x + threadIdx.x;
    if (i < NN) {
        int r = g_rs[i] + g_boff[i / SCAN_BS];
        g_rs[i] = r;
        g_cur[i] = r;
    }
    if (i == 0) g_rs[NN] = NE;
}

// ---------------- fused norm + record scatter --------------------------------
__global__ void k_normbuild(const int* __restrict__ src, const int* __restrict__ dst,
                            const float* __restrict__ w) {
    int e = blockIdx.x * blockDim.x + threadIdx.x;
    if (e >= NE) return;
    int s = src[e], d = dst[e];
    float we = (s == d) ? 0.f : w[e];
    float ds = g_deg[s], dd = g_deg[d];
    float is = (ds > 0.f) ? rsqrtf(ds) : 0.f;
    float id = (dd > 0.f) ? rsqrtf(dd) : 0.f;
    float norm = -is * we * id;
    int p = atomicAdd(&g_cur[d], 1);
    g_recs[p] = make_int2(s, __float_as_int(norm));
}

// ---------------- layer 1 init: T0 = pad(x), O1 = x @ W1[0] ------------------
__global__ void k_l1_init(const float* __restrict__ x, const float* __restrict__ W0) {
    __shared__ float sW[FIN * HID];
    for (int i = threadIdx.x; i < FIN * HID; i += blockDim.x) sW[i] = W0[i];
    __syncthreads();
    int n = blockIdx.x * blockDim.x + threadIdx.x;
    if (n >= NN) return;
    float t[FIN];
    const float* xr = x + (size_t)n * FIN;
#pragma unroll
    for (int i = 0; i < FIN; i++) t[i] = xr[i];
    float* a = g_T0 + (size_t)n * S1;
#pragma unroll
    for (int i = 0; i < FIN; i++) a[i] = t[i];
#pragma unroll
    for (int i = FIN; i < S1; i++) a[i] = 0.f;
    float* o = g_O1 + (size_t)n * S2;
#pragma unroll
    for (int j = 0; j < HID; j++) {
        float acc = 0.f;
#pragma unroll
        for (int i = 0; i < FIN; i++) acc += t[i] * sW[i * HID + j];
        o[j] = acc;
    }
}

// ---------------- warp-per-node CSR gather props -----------------------------
// hout[n] = (Tprev ? -Tprev[n] : 0) + sum_{e in in(n)} scale*norm_e * hin[src_e]
// prop10: 8 edge-subgroups x 4 lanes (off = float4 slot of 16-float row).
__global__ void k_prop10(const float* __restrict__ hin, const float* __restrict__ Tprev,
                         float* __restrict__ hout, float scale) {
    int warp = (blockIdx.x * blockDim.x + threadIdx.x) >> 5;
    int lane = threadIdx.x & 31;
    if (warp >= NN) return;
    int n = warp;
    int off = lane & 3;          // float4 slot
    int sub = lane >> 2;         // 0..7 edge subgroup
    int s = g_rs[n], e = g_rs[n + 1];
    float4 acc = make_float4(0.f, 0.f, 0.f, 0.f);
    int i = s + sub;
    for (; i + 8 < e; i += 16) {   // 2 chains/lane x 8 subgroups = MLP 16
        int2 r0 = g_recs[i], r1 = g_recs[i + 8];
        float c0 = __int_as_float(r0.y) * scale;
        float c1 = __int_as_float(r1.y) * scale;
        float4 v0 = *(const float4*)(hin + ((size_t)r0.x << 4) + (off << 2));
        float4 v1 = *(const float4*)(hin + ((size_t)r1.x << 4) + (off << 2));
        acc.x += c0 * v0.x + c1 * v1.x;
        acc.y += c0 * v0.y + c1 * v1.y;
        acc.z += c0 * v0.z + c1 * v1.z;
        acc.w += c0 * v0.w + c1 * v1.w;
    }
    if (i < e) {
        int2 r = g_recs[i];
        float c = __int_as_float(r.y) * scale;
        float4 v = *(const float4*)(hin + ((size_t)r.x << 4) + (off << 2));
        acc.x += c * v.x; acc.y += c * v.y; acc.z += c * v.z; acc.w += c * v.w;
    }
    // fold the 8 subgroups (stride 4, 8, 16)
#pragma unroll
    for (int m = 4; m <= 16; m <<= 1) {
        acc.x += __shfl_xor_sync(0xFFFFFFFF, acc.x, m);
        acc.y += __shfl_xor_sync(0xFFFFFFFF, acc.y, m);
        acc.z += __shfl_xor_sync(0xFFFFFFFF, acc.z, m);
        acc.w += __shfl_xor_sync(0xFFFFFFFF, acc.w, m);
    }
    if (lane < 4) {
        if (Tprev) {
            float4 v = *(const float4*)(Tprev + ((size_t)n << 4) + (off << 2));
            acc.x -= v.x; acc.y -= v.y; acc.z -= v.z; acc.w -= v.w;
        }
        *(float4*)(hout + ((size_t)n << 4) + (off << 2)) = acc;
    }
}

// prop30: 4 edge-subgroups x 8 lanes (off = float4 slot of 32-float row).
__global__ void k_prop30(const float* __restrict__ hin, const float* __restrict__ Tprev,
                         float* __restrict__ hout, float scale) {
    int warp = (blockIdx.x * blockDim.x + threadIdx.x) >> 5;
    int lane = threadIdx.x & 31;
    if (warp >= NN) return;
    int n = warp;
    int off = lane & 7;          // float4 slot
    int sub = lane >> 3;         // 0..3 edge subgroup
    int s = g_rs[n], e = g_rs[n + 1];
    float4 acc = make_float4(0.f, 0.f, 0.f, 0.f);
    int i = s + sub;
    for (; i + 4 < e; i += 8) {    // 2 chains/lane x 4 subgroups = MLP 8
        int2 r0 = g_recs[i], r1 = g_recs[i + 4];
        float c0 = __int_as_float(r0.y) * scale;
        float c1 = __int_as_float(r1.y) * scale;
        float4 v0 = *(const float4*)(hin + ((size_t)r0.x << 5) + (off << 2));
        float4 v1 = *(const float4*)(hin + ((size_t)r1.x << 5) + (off << 2));
        acc.x += c0 * v0.x + c1 * v1.x;
        acc.y += c0 * v0.y + c1 * v1.y;
        acc.z += c0 * v0.z + c1 * v1.z;
        acc.w += c0 * v0.w + c1 * v1.w;
    }
    if (i < e) {
        int2 r = g_recs[i];
        float c = __int_as_float(r.y) * scale;
        float4 v = *(const float4*)(hin + ((size_t)r.x << 5) + (off << 2));
        acc.x += c * v.x; acc.y += c * v.y; acc.z += c * v.z; acc.w += c * v.w;
    }
    // fold the 4 subgroups (stride 8, 16)
#pragma unroll
    for (int m = 8; m <= 16; m <<= 1) {
        acc.x += __shfl_xor_sync(0xFFFFFFFF, acc.x, m);
        acc.y += __shfl_xor_sync(0xFFFFFFFF, acc.y, m);
        acc.z += __shfl_xor_sync(0xFFFFFFFF, acc.z, m);
        acc.w += __shfl_xor_sync(0xFFFFFFFF, acc.w, m);
    }
    if (lane < 8) {
        if (Tprev) {
            float4 v = *(const float4*)(Tprev + ((size_t)n << 5) + (off << 2));
            acc.x -= v.x; acc.y -= v.y; acc.z -= v.z; acc.w -= v.w;
        }
        *(float4*)(hout + ((size_t)n << 5) + (off << 2)) = acc;
    }
}

// ---------------- node matvec steps (accumulate only) ------------------------
__global__ void k_l1_node(const float* __restrict__ Tnew, const float* __restrict__ Wk) {
    __shared__ float sW[FIN * HID];
    for (int i = threadIdx.x; i < FIN * HID; i += blockDim.x) sW[i] = Wk[i];
    __syncthreads();
    int n = blockIdx.x * blockDim.x + threadIdx.x;
    if (n >= NN) return;
    const float* tr = Tnew + (size_t)n * S1;
    float t[FIN];
#pragma unroll
    for (int i = 0; i < FIN; i++) t[i] = tr[i];
    float* o = g_O1 + (size_t)n * S2;
#pragma unroll
    for (int j = 0; j < HID; j++) {
        float acc = o[j];
#pragma unroll
        for (int i = 0; i < FIN; i++) acc += t[i] * sW[i * HID + j];
        o[j] = acc;
    }
}

__global__ void k_l2_node(const float* __restrict__ Tnew, const float* __restrict__ Wk) {
    __shared__ float sW[HID * HID];
    for (int i = threadIdx.x; i < HID * HID; i += blockDim.x) sW[i] = Wk[i];
    __syncthreads();
    int n = blockIdx.x * blockDim.x + threadIdx.x;
    if (n >= NN) return;
    const float* tr = Tnew + (size_t)n * S2;
    float t[HID];
#pragma unroll
    for (int i = 0; i < HID; i++) t[i] = tr[i];
    float* o = g_O2 + (size_t)n * S2;
#pragma unroll
    for (int j = 0; j < HID; j++) {
        float acc = o[j];
#pragma unroll
        for (int i = 0; i < HID; i++) acc += t[i] * sW[i * HID + j];
        o[j] = acc;
    }
}

// -------- layer-1 final: h=relu(O1+T4@W1[4]+b1); A2=h (pads 0), O2=h@W2[0] ---
__global__ void k_l1_final(const float* __restrict__ Tnew,
                           const float* __restrict__ W14, const float* __restrict__ b1,
                           const float* __restrict__ W20) {
    __shared__ float sW4[FIN * HID];
    __shared__ float sW0[HID * HID];
    __shared__ float sb[HID];
    for (int i = threadIdx.x; i < FIN * HID; i += blockDim.x) sW4[i] = W14[i];
    for (int i = threadIdx.x; i < HID * HID; i += blockDim.x) sW0[i] = W20[i];
    for (int i = threadIdx.x; i < HID; i += blockDim.x) sb[i] = b1[i];
    __syncthreads();
    int n = blockIdx.x * blockDim.x + threadIdx.x;
    if (n >= NN) return;
    const float* tr = Tnew + (size_t)n * S1;
    float t[FIN];
#pragma unroll
    for (int i = 0; i < FIN; i++) t[i] = tr[i];
    float* o1 = g_O1 + (size_t)n * S2;
    float h[HID];
#pragma unroll
    for (int j = 0; j < HID; j++) {
        float acc = o1[j];
#pragma unroll
        for (int i = 0; i < FIN; i++) acc += t[i] * sW4[i * HID + j];
        h[j] = fmaxf(acc + sb[j], 0.f);
    }
    float* a2 = g_A2 + (size_t)n * S2;
#pragma unroll
    for (int j = 0; j < HID; j++) a2[j] = h[j];
    a2[30] = 0.f; a2[31] = 0.f;
    float* o2 = g_O2 + (size_t)n * S2;
#pragma unroll
    for (int j = 0; j < HID; j++) {
        float acc = 0.f;
#pragma unroll
        for (int i = 0; i < HID; i++) acc += h[i] * sW0[i * HID + j];
        o2[j] = acc;
    }
}

// -------- layer-2 final + head: out = relu(O2+T4@W2[4]+b2) @ Wl + bl ---------
__global__ void k_l2_final(const float* __restrict__ Tnew,
                           const float* __restrict__ W24, const float* __restrict__ b2,
                           const float* __restrict__ Wl, const float* __restrict__ bl,
                           float* __restrict__ out) {
    __shared__ float sW4[HID * HID];
    __shared__ float sWl[HID * NCLS];
    __shared__ float sb2[HID];
    __shared__ float sbl[NCLS];
    for (int i = threadIdx.x; i < HID * HID; i += blockDim.x) sW4[i] = W24[i];
    for (int i = threadIdx.x; i < HID * NCLS; i += blockDim.x) sWl[i] = Wl[i];
    for (int i = threadIdx.x; i < HID; i += blockDim.x) sb2[i] = b2[i];
    for (int i = threadIdx.x; i < NCLS; i += blockDim.x) sbl[i] = bl[i];
    __syncthreads();
    int n = blockIdx.x * blockDim.x + threadIdx.x;
    if (n >= NN) return;
    const float* tr = Tnew + (size_t)n * S2;
    float t[HID];
#pragma unroll
    for (int i = 0; i < HID; i++) t[i] = tr[i];
    float* o2 = g_O2 + (size_t)n * S2;
    float h[HID];
#pragma unroll
    for (int j = 0; j < HID; j++) {
        float acc = o2[j];
#pragma unroll
        for (int i = 0; i < HID; i++) acc += t[i] * sW4[i * HID + j];
        h[j] = fmaxf(acc + sb2[j], 0.f);
    }
    float r[NCLS];
#pragma unroll
    for (int c = 0; c < NCLS; c++) {
        float acc = sbl[c];
#pragma unroll
        for (int j = 0; j < HID; j++) acc += h[j] * sWl[j * NCLS + c];
        r[c] = acc;
    }
    *(float4*)(out + (size_t)n * NCLS) = make_float4(r[0], r[1], r[2], r[3]);
}

// ---------------- launch -----------------------------------------------------
extern "C" void kernel_launch(void* const* d_in, const int* in_sizes, int n_in,
                              void* d_out, int out_size) {
    const float* x  = (const float*)d_in[0];
    const int*   ei = (const int*)d_in[1];
    const float* ew = (const float*)d_in[2];
    const float* W1 = (const float*)d_in[3];
    const float* b1 = (const float*)d_in[4];
    const float* W2 = (const float*)d_in[5];
    const float* b2 = (const float*)d_in[6];
    const float* Wl = (const float*)d_in[7];
    const float* bl = (const float*)d_in[8];
    float* out = (float*)d_out;

    const int* src = ei;
    const int* dst = ei + NE;

    float *T0, *T1, *T2, *A2, *B2, *C2;
    cudaGetSymbolAddress((void**)&T0, g_T0);
    cudaGetSymbolAddress((void**)&T1, g_T1);
    cudaGetSymbolAddress((void**)&T2, g_T2);
    cudaGetSymbolAddress((void**)&A2, g_A2);
    cudaGetSymbolAddress((void**)&B2, g_B2);
    cudaGetSymbolAddress((void**)&C2, g_C2);

    dim3 blk(256);
    dim3 ng((NN + 255) / 256);
    dim3 eg((NE + 255) / 256);
    dim3 nw((NN * 32 + 255) / 256);   // warp-per-node prop grids

    // CSR build
    k_zero<<<ng, blk>>>();
    k_deg<<<eg, blk>>>(src, dst, ew);
    k_scan1<<<SCAN_NB, SCAN_BS>>>();
    k_scan2<<<1, 256>>>();
    k_scan3<<<ng, blk>>>();
    k_normbuild<<<eg, blk>>>(src, dst, ew);

    // ---- layer 1 (dim 10, stride 16) ----
    k_l1_init<<<ng, blk>>>(x, W1 + 0 * FIN * HID);
    k_prop10<<<nw, blk>>>(T0, nullptr, T1, 1.0f);             // T1 = S T0
    k_l1_node<<<ng, blk>>>(T1, W1 + 1 * FIN * HID);
    k_prop10<<<nw, blk>>>(T1, T0, T2, 2.0f);                  // T2 = 2S T1 - T0
    k_l1_node<<<ng, blk>>>(T2, W1 + 2 * FIN * HID);
    k_prop10<<<nw, blk>>>(T2, T1, T0, 2.0f);                  // T3 (into T0)
    k_l1_node<<<ng, blk>>>(T0, W1 + 3 * FIN * HID);
    k_prop10<<<nw, blk>>>(T0, T2, T1, 2.0f);                  // T4 (into T1)
    k_l1_final<<<ng, blk>>>(T1, W1 + 4 * FIN * HID, b1, W2 + 0 * HID * HID);

    // ---- layer 2 (dim 30, stride 32) ----
    k_prop30<<<nw, blk>>>(A2, nullptr, B2, 1.0f);             // T1
    k_l2_node<<<ng, blk>>>(B2, W2 + 1 * HID * HID);
    k_prop30<<<nw, blk>>>(B2, A2, C2, 2.0f);                  // T2
    k_l2_node<<<ng, blk>>>(C2, W2 + 2 * HID * HID);
    k_prop30<<<nw, blk>>>(C2, B2, A2, 2.0f);                  // T3 (into A2)
    k_l2_node<<<ng, blk>>>(A2, W2 + 3 * HID * HID);
    k_prop30<<<nw, blk>>>(A2, C2, B2, 2.0f);                  // T4 (into B2)
    k_l2_final<<<ng, blk>>>(B2, W2 + 4 * HID * HID, b2, Wl, bl, out);
}

// round 8
// speedup vs baseline: 2.7064x; 1.0836x over previous
#include <cuda_runtime.h>
#include <cstddef>

#define NN   100000
#define NE   3200000
#define FIN  10
#define HID  30
#define NCLS 4
#define S1   12   // layer-1 row stride (floats): 10 -> 12 (48B, 16B-aligned rows)
#define S2   32   // layer-2 row stride (floats): 30 -> 32 (128B)

#define SCAN_BS 512
#define SCAN_NB ((NN + SCAN_BS - 1) / SCAN_BS)   // 196

// ---------------- scratch (static device globals) ---------------------------
__device__ __align__(16) float g_deg[NN];
__device__ __align__(16) int   g_cnt[NN];
__device__ __align__(16) int   g_rs[NN + 1];     // CSR row starts (by dst)
__device__ __align__(16) int   g_cur[NN];        // scatter cursors
__device__ __align__(16) int   g_bsum[SCAN_NB];
__device__ __align__(16) int   g_boff[SCAN_NB];
__device__ __align__(16) int2  g_recs[NE];       // {src, norm bits} sorted by dst
__device__ __align__(16) float g_T0[NN * S1];
__device__ __align__(16) float g_T1[NN * S1];
__device__ __align__(16) float g_T2[NN * S1];
__device__ __align__(16) float g_A2[NN * S2];
__device__ __align__(16) float g_B2[NN * S2];
__device__ __align__(16) float g_C2[NN * S2];
__device__ __align__(16) float g_O1[NN * S2];
__device__ __align__(16) float g_O2[NN * S2];

// ---------------- degree + histogram -----------------------------------------
__global__ void k_zero() {
    int i = blockIdx.x * blockDim.x + threadIdx.x;
    if (i < NN) { g_deg[i] = 0.f; g_cnt[i] = 0; }
}

__global__ void k_deg(const int* __restrict__ src, const int* __restrict__ dst,
                      const float* __restrict__ w) {
    int e = blockIdx.x * blockDim.x + threadIdx.x;
    if (e >= NE) return;
    int s = src[e], d = dst[e];
    if (s != d) atomicAdd(&g_deg[s], w[e]);
    atomicAdd(&g_cnt[d], 1);
}

// ---------------- CSR build: 2-level exclusive scan --------------------------
__global__ void k_scan1() {
    __shared__ int sh[SCAN_BS];
    int tid = threadIdx.x;
    int i = blockIdx.x * SCAN_BS + tid;
    int v = (i < NN) ? g_cnt[i] : 0;
    sh[tid] = v;
    __syncthreads();
#pragma unroll
    for (int ofs = 1; ofs < SCAN_BS; ofs <<= 1) {
        int t = (tid >= ofs) ? sh[tid - ofs] : 0;
        __syncthreads();
        sh[tid] += t;
        __syncthreads();
    }
    if (i < NN) g_rs[i] = sh[tid] - v;            // exclusive
    if (tid == SCAN_BS - 1) g_bsum[blockIdx.x] = sh[tid];
}

__global__ void k_scan2() {
    __shared__ int sh[256];
    int tid = threadIdx.x;
    int v = (tid < SCAN_NB) ? g_bsum[tid] : 0;
    sh[tid] = v;
    __syncthreads();
#pragma unroll
    for (int ofs = 1; ofs < 256; ofs <<= 1) {
        int t = (tid >= ofs) ? sh[tid - ofs] : 0;
        __syncthreads();
        sh[tid] += t;
        __syncthreads();
    }
    if (tid < SCAN_NB) g_boff[tid] = sh[tid] - v; // exclusive
}

__global__ void k_scan3() {
    int i = blockIdx.x * blockDim.x + threadIdx.x;
    if (i < NN) {
        int r = g_rs[i] + g_boff[i / SCAN_BS];
        g_rs[i] = r;
        g_cur[i] = r;
    }
    if (i == 0) g_rs[NN] = NE;
}

// ---------------- fused norm + record scatter --------------------------------
__global__ void k_normbuild(const int* __restrict__ src, const int* __restrict__ dst,
                            const float* __restrict__ w) {
    int e = blockIdx.x * blockDim.x + threadIdx.x;
    if (e >= NE) return;
    int s = src[e], d = dst[e];
    float we = (s == d) ? 0.f : w[e];
    float ds = g_deg[s], dd = g_deg[d];
    float is = (ds > 0.f) ? rsqrtf(ds) : 0.f;
    float id = (dd > 0.f) ? rsqrtf(dd) : 0.f;
    float norm = -is * we * id;
    int p = atomicAdd(&g_cur[d], 1);
    g_recs[p] = make_int2(s, __float_as_int(norm));
}

// ---------------- layer 1 init: T0 = pad(x), O1 = x @ W1[0] ------------------
// Padded smem weights (rows of 32) for float4 LDS.
__global__ void k_l1_init(const float* __restrict__ x, const float* __restrict__ W0) {
    __shared__ __align__(16) float sWp[FIN * 32];
    for (int i = threadIdx.x; i < FIN * 32; i += blockDim.x) {
        int r = i >> 5, c = i & 31;
        sWp[i] = (c < HID) ? W0[r * HID + c] : 0.f;
    }
    __syncthreads();
    int n = blockIdx.x * blockDim.x + threadIdx.x;
    if (n >= NN) return;
    float t[FIN];
    const float* xr = x + (size_t)n * FIN;
#pragma unroll
    for (int i = 0; i < FIN; i++) t[i] = xr[i];
    float4* a = (float4*)(g_T0 + (size_t)n * S1);
    a[0] = make_float4(t[0], t[1], t[2], t[3]);
    a[1] = make_float4(t[4], t[5], t[6], t[7]);
    a[2] = make_float4(t[8], t[9], 0.f, 0.f);
    float4 acc[8];
#pragma unroll
    for (int q = 0; q < 8; q++) acc[q] = make_float4(0.f, 0.f, 0.f, 0.f);
#pragma unroll
    for (int i = 0; i < FIN; i++) {
        const float4* wr = (const float4*)(sWp + i * 32);
#pragma unroll
        for (int q = 0; q < 8; q++) {
            float4 wv = wr[q];
            acc[q].x += t[i] * wv.x; acc[q].y += t[i] * wv.y;
            acc[q].z += t[i] * wv.z; acc[q].w += t[i] * wv.w;
        }
    }
    float4* o = (float4*)(g_O1 + (size_t)n * S2);
#pragma unroll
    for (int q = 0; q < 8; q++) o[q] = acc[q];
}

// ---------------- warp-per-node CSR gather props -----------------------------
// prop10: 8 edge-subgroups x 4 lanes; rows are 12 floats (3 float4 slots);
// lane with off==3 idles on loads (row has only 3 slots).
__global__ void k_prop10(const float* __restrict__ hin, const float* __restrict__ Tprev,
                         float* __restrict__ hout, float scale) {
    int warp = (blockIdx.x * blockDim.x + threadIdx.x) >> 5;
    int lane = threadIdx.x & 31;
    if (warp >= NN) return;
    int n = warp;
    int off = lane & 3;          // float4 slot (0..2 real, 3 idle)
    int sub = lane >> 2;         // 0..7 edge subgroup
    int s = g_rs[n], e = g_rs[n + 1];
    float4 acc = make_float4(0.f, 0.f, 0.f, 0.f);
    bool live = (off < 3);
    int i = s + sub;
    for (; i + 8 < e; i += 16) {
        int2 r0 = g_recs[i], r1 = g_recs[i + 8];
        if (live) {
            float c0 = __int_as_float(r0.y) * scale;
            float c1 = __int_as_float(r1.y) * scale;
            float4 v0 = *(const float4*)(hin + (size_t)r0.x * S1 + (off << 2));
            float4 v1 = *(const float4*)(hin + (size_t)r1.x * S1 + (off << 2));
            acc.x += c0 * v0.x + c1 * v1.x;
            acc.y += c0 * v0.y + c1 * v1.y;
            acc.z += c0 * v0.z + c1 * v1.z;
            acc.w += c0 * v0.w + c1 * v1.w;
        }
    }
    if (i < e && live) {
        int2 r = g_recs[i];
        float c = __int_as_float(r.y) * scale;
        float4 v = *(const float4*)(hin + (size_t)r.x * S1 + (off << 2));
        acc.x += c * v.x; acc.y += c * v.y; acc.z += c * v.z; acc.w += c * v.w;
    }
#pragma unroll
    for (int m = 4; m <= 16; m <<= 1) {
        acc.x += __shfl_xor_sync(0xFFFFFFFF, acc.x, m);
        acc.y += __shfl_xor_sync(0xFFFFFFFF, acc.y, m);
        acc.z += __shfl_xor_sync(0xFFFFFFFF, acc.z, m);
        acc.w += __shfl_xor_sync(0xFFFFFFFF, acc.w, m);
    }
    if (lane < 3) {
        if (Tprev) {
            float4 v = *(const float4*)(Tprev + (size_t)n * S1 + (lane << 2));
            acc.x -= v.x; acc.y -= v.y; acc.z -= v.z; acc.w -= v.w;
        }
        *(float4*)(hout + (size_t)n * S1 + (lane << 2)) = acc;
    }
}

// prop30: 4 edge-subgroups x 8 lanes (off = float4 slot of 32-float row).
__global__ void k_prop30(const float* __restrict__ hin, const float* __restrict__ Tprev,
                         float* __restrict__ hout, float scale) {
    int warp = (blockIdx.x * blockDim.x + threadIdx.x) >> 5;
    int lane = threadIdx.x & 31;
    if (warp >= NN) return;
    int n = warp;
    int off = lane & 7;
    int sub = lane >> 3;
    int s = g_rs[n], e = g_rs[n + 1];
    float4 acc = make_float4(0.f, 0.f, 0.f, 0.f);
    int i = s + sub;
    for (; i + 4 < e; i += 8) {
        int2 r0 = g_recs[i], r1 = g_recs[i + 4];
        float c0 = __int_as_float(r0.y) * scale;
        float c1 = __int_as_float(r1.y) * scale;
        float4 v0 = *(const float4*)(hin + ((size_t)r0.x << 5) + (off << 2));
        float4 v1 = *(const float4*)(hin + ((size_t)r1.x << 5) + (off << 2));
        acc.x += c0 * v0.x + c1 * v1.x;
        acc.y += c0 * v0.y + c1 * v1.y;
        acc.z += c0 * v0.z + c1 * v1.z;
        acc.w += c0 * v0.w + c1 * v1.w;
    }
    if (i < e) {
        int2 r = g_recs[i];
        float c = __int_as_float(r.y) * scale;
        float4 v = *(const float4*)(hin + ((size_t)r.x << 5) + (off << 2));
        acc.x += c * v.x; acc.y += c * v.y; acc.z += c * v.z; acc.w += c * v.w;
    }
#pragma unroll
    for (int m = 8; m <= 16; m <<= 1) {
        acc.x += __shfl_xor_sync(0xFFFFFFFF, acc.x, m);
        acc.y += __shfl_xor_sync(0xFFFFFFFF, acc.y, m);
        acc.z += __shfl_xor_sync(0xFFFFFFFF, acc.z, m);
        acc.w += __shfl_xor_sync(0xFFFFFFFF, acc.w, m);
    }
    if (lane < 8) {
        if (Tprev) {
            float4 v = *(const float4*)(Tprev + ((size_t)n << 5) + (off << 2));
            acc.x -= v.x; acc.y -= v.y; acc.z -= v.z; acc.w -= v.w;
        }
        *(float4*)(hout + ((size_t)n << 5) + (off << 2)) = acc;
    }
}

// ---------------- node matvec steps (float4-vectorized) ----------------------
__global__ void k_l1_node(const float* __restrict__ Tnew, const float* __restrict__ Wk) {
    __shared__ __align__(16) float sWp[FIN * 32];
    for (int i = threadIdx.x; i < FIN * 32; i += blockDim.x) {
        int r = i >> 5, c = i & 31;
        sWp[i] = (c < HID) ? Wk[r * HID + c] : 0.f;
    }
    __syncthreads();
    int n = blockIdx.x * blockDim.x + threadIdx.x;
    if (n >= NN) return;
    const float4* tr = (const float4*)(Tnew + (size_t)n * S1);
    float4 t0 = tr[0], t1 = tr[1], t2 = tr[2];
    float t[FIN] = {t0.x, t0.y, t0.z, t0.w, t1.x, t1.y, t1.z, t1.w, t2.x, t2.y};
    float4* o = (float4*)(g_O1 + (size_t)n * S2);
    float4 acc[8];
#pragma unroll
    for (int q = 0; q < 8; q++) acc[q] = o[q];
#pragma unroll
    for (int i = 0; i < FIN; i++) {
        const float4* wr = (const float4*)(sWp + i * 32);
#pragma unroll
        for (int q = 0; q < 8; q++) {
            float4 wv = wr[q];
            acc[q].x += t[i] * wv.x; acc[q].y += t[i] * wv.y;
            acc[q].z += t[i] * wv.z; acc[q].w += t[i] * wv.w;
        }
    }
#pragma unroll
    for (int q = 0; q < 8; q++) o[q] = acc[q];
}

__global__ void k_l2_node(const float* __restrict__ Tnew, const float* __restrict__ Wk) {
    __shared__ __align__(16) float sWp[HID * 32];
    for (int i = threadIdx.x; i < HID * 32; i += blockDim.x) {
        int r = i >> 5, c = i & 31;
        sWp[i] = (c < HID) ? Wk[r * HID + c] : 0.f;
    }
    __syncthreads();
    int n = blockIdx.x * blockDim.x + threadIdx.x;
    if (n >= NN) return;
    const float4* tr = (const float4*)(Tnew + (size_t)n * S2);
    float4 tt[8];
#pragma unroll
    for (int q = 0; q < 8; q++) tt[q] = tr[q];
    float t[HID] = {tt[0].x, tt[0].y, tt[0].z, tt[0].w, tt[1].x, tt[1].y, tt[1].z, tt[1].w,
                    tt[2].x, tt[2].y, tt[2].z, tt[2].w, tt[3].x, tt[3].y, tt[3].z, tt[3].w,
                    tt[4].x, tt[4].y, tt[4].z, tt[4].w, tt[5].x, tt[5].y, tt[5].z, tt[5].w,
                    tt[6].x, tt[6].y, tt[6].z, tt[6].w, tt[7].x, tt[7].y};
    float4* o = (float4*)(g_O2 + (size_t)n * S2);
    float4 acc[8];
#pragma unroll
    for (int q = 0; q < 8; q++) acc[q] = o[q];
#pragma unroll
    for (int i = 0; i < HID; i++) {
        const float4* wr = (const float4*)(sWp + i * 32);
#pragma unroll
        for (int q = 0; q < 8; q++) {
            float4 wv = wr[q];
            acc[q].x += t[i] * wv.x; acc[q].y += t[i] * wv.y;
            acc[q].z += t[i] * wv.z; acc[q].w += t[i] * wv.w;
        }
    }
#pragma unroll
    for (int q = 0; q < 8; q++) o[q] = acc[q];
}

// -------- layer-1 final: h=relu(O1+T4@W1[4]+b1); A2=h (pads 0), O2=h@W2[0] ---
__global__ void k_l1_final(const float* __restrict__ Tnew,
                           const float* __restrict__ W14, const float* __restrict__ b1,
                           const float* __restrict__ W20) {
    __shared__ __align__(16) float sW4p[FIN * 32];
    __shared__ __align__(16) float sW0p[HID * 32];
    __shared__ float sb[HID];
    for (int i = threadIdx.x; i < FIN * 32; i += blockDim.x) {
        int r = i >> 5, c = i & 31;
        sW4p[i] = (c < HID) ? W14[r * HID + c] : 0.f;
    }
    for (int i = threadIdx.x; i < HID * 32; i += blockDim.x) {
        int r = i >> 5, c = i & 31;
        sW0p[i] = (c < HID) ? W20[r * HID + c] : 0.f;
    }
    for (int i = threadIdx.x; i < HID; i += blockDim.x) sb[i] = b1[i];
    __syncthreads();
    int n = blockIdx.x * blockDim.x + threadIdx.x;
    if (n >= NN) return;
    const float4* tr = (const float4*)(Tnew + (size_t)n * S1);
    float4 t0 = tr[0], t1 = tr[1], t2 = tr[2];
    float t[FIN] = {t0.x, t0.y, t0.z, t0.w, t1.x, t1.y, t1.z, t1.w, t2.x, t2.y};
    const float4* o1 = (const float4*)(g_O1 + (size_t)n * S2);
    float4 acc[8];
#pragma unroll
    for (int q = 0; q < 8; q++) acc[q] = o1[q];
#pragma unroll
    for (int i = 0; i < FIN; i++) {
        const float4* wr = (const float4*)(sW4p + i * 32);
#pragma unroll
        for (int q = 0; q < 8; q++) {
            float4 wv = wr[q];
            acc[q].x += t[i] * wv.x; acc[q].y += t[i] * wv.y;
            acc[q].z += t[i] * wv.z; acc[q].w += t[i] * wv.w;
        }
    }
    float h[HID];
#pragma unroll
    for (int j = 0; j < HID; j++) {
        float v = ((const float*)acc)[j];
        h[j] = fmaxf(v + sb[j], 0.f);
    }
    // A2 = h with pads zero
    float4* a2 = (float4*)(g_A2 + (size_t)n * S2);
#pragma unroll
    for (int q = 0; q < 7; q++)
        a2[q] = make_float4(h[q * 4], h[q * 4 + 1], h[q * 4 + 2], h[q * 4 + 3]);
    a2[7] = make_float4(h[28], h[29], 0.f, 0.f);
    // O2 = h @ W2[0]
    float4 acc2[8];
#pragma unroll
    for (int q = 0; q < 8; q++) acc2[q] = make_float4(0.f, 0.f, 0.f, 0.f);
#pragma unroll
    for (int i = 0; i < HID; i++) {
        const float4* wr = (const float4*)(sW0p + i * 32);
#pragma unroll
        for (int q = 0; q < 8; q++) {
            float4 wv = wr[q];
            acc2[q].x += h[i] * wv.x; acc2[q].y += h[i] * wv.y;
            acc2[q].z += h[i] * wv.z; acc2[q].w += h[i] * wv.w;
        }
    }
    float4* o2 = (float4*)(g_O2 + (size_t)n * S2);
#pragma unroll
    for (int q = 0; q < 8; q++) o2[q] = acc2[q];
}

// -------- layer-2 final + head: out = relu(O2+T4@W2[4]+b2) @ Wl + bl ---------
__global__ void k_l2_final(const float* __restrict__ Tnew,
                           const float* __restrict__ W24, const float* __restrict__ b2,
                           const float* __restrict__ Wl, const float* __restrict__ bl,
                           float* __restrict__ out) {
    __shared__ __align__(16) float sW4p[HID * 32];
    __shared__ float sWl[HID * NCLS];
    __shared__ float sb2[HID];
    __shared__ float sbl[NCLS];
    for (int i = threadIdx.x; i < HID * 32; i += blockDim.x) {
        int r = i >> 5, c = i & 31;
        sW4p[i] = (c < HID) ? W24[r * HID + c] : 0.f;
    }
    for (int i = threadIdx.x; i < HID * NCLS; i += blockDim.x) sWl[i] = Wl[i];
    for (int i = threadIdx.x; i < HID; i += blockDim.x) sb2[i] = b2[i];
    for (int i = threadIdx.x; i < NCLS; i += blockDim.x) sbl[i] = bl[i];
    __syncthreads();
    int n = blockIdx.x * blockDim.x + threadIdx.x;
    if (n >= NN) return;
    const float4* tr = (const float4*)(Tnew + (size_t)n * S2);
    float4 tt[8];
#pragma unroll
    for (int q = 0; q < 8; q++) tt[q] = tr[q];
    float t[HID] = {tt[0].x, tt[0].y, tt[0].z, tt[0].w, tt[1].x, tt[1].y, tt[1].z, tt[1].w,
                    tt[2].x, tt[2].y, tt[2].z, tt[2].w, tt[3].x, tt[3].y, tt[3].z, tt[3].w,
                    tt[4].x, tt[4].y, tt[4].z, tt[4].w, tt[5].x, tt[5].y, tt[5].z, tt[5].w,
                    tt[6].x, tt[6].y, tt[6].z, tt[6].w, tt[7].x, tt[7].y};
    const float4* o2 = (const float4*)(g_O2 + (size_t)n * S2);
    float4 acc[8];
#pragma unroll
    for (int q = 0; q < 8; q++) acc[q] = o2[q];
#pragma unroll
    for (int i = 0; i < HID; i++) {
        const float4* wr = (const float4*)(sW4p + i * 32);
#pragma unroll
        for (int q = 0; q < 8; q++) {
            float4 wv = wr[q];
            acc[q].x += t[i] * wv.x; acc[q].y += t[i] * wv.y;
            acc[q].z += t[i] * wv.z; acc[q].w += t[i] * wv.w;
        }
    }
    float h[HID];
#pragma unroll
    for (int j = 0; j < HID; j++) {
        float v = ((const float*)acc)[j];
        h[j] = fmaxf(v + sb2[j], 0.f);
    }
    float r[NCLS];
#pragma unroll
    for (int c = 0; c < NCLS; c++) r[c] = sbl[c];
#pragma unroll
    for (int j = 0; j < HID; j++) {
#pragma unroll
        for (int c = 0; c < NCLS; c++) r[c] += h[j] * sWl[j * NCLS + c];
    }
    *(float4*)(out + (size_t)n * NCLS) = make_float4(r[0], r[1], r[2], r[3]);
}

// ---------------- launch -----------------------------------------------------
extern "C" void kernel_launch(void* const* d_in, const int* in_sizes, int n_in,
                              void* d_out, int out_size) {
    const float* x  = (const float*)d_in[0];
    const int*   ei = (const int*)d_in[1];
    const float* ew = (const float*)d_in[2];
    const float* W1 = (const float*)d_in[3];
    const float* b1 = (const float*)d_in[4];
    const float* W2 = (const float*)d_in[5];
    const float* b2 = (const float*)d_in[6];
    const float* Wl = (const float*)d_in[7];
    const float* bl = (const float*)d_in[8];
    float* out = (float*)d_out;

    const int* src = ei;
    const int* dst = ei + NE;

    float *T0, *T1, *T2, *A2, *B2, *C2;
    cudaGetSymbolAddress((void**)&T0, g_T0);
    cudaGetSymbolAddress((void**)&T1, g_T1);
    cudaGetSymbolAddress((void**)&T2, g_T2);
    cudaGetSymbolAddress((void**)&A2, g_A2);
    cudaGetSymbolAddress((void**)&B2, g_B2);
    cudaGetSymbolAddress((void**)&C2, g_C2);

    dim3 blk(256);
    dim3 ng((NN + 255) / 256);
    dim3 eg((NE + 255) / 256);
    dim3 nw((NN * 32 + 255) / 256);   // warp-per-node prop grids

    // CSR build
    k_zero<<<ng, blk>>>();
    k_deg<<<eg, blk>>>(src, dst, ew);
    k_scan1<<<SCAN_NB, SCAN_BS>>>();
    k_scan2<<<1, 256>>>();
    k_scan3<<<ng, blk>>>();
    k_normbuild<<<eg, blk>>>(src, dst, ew);

    // ---- layer 1 (dim 10, stride 12) ----
    k_l1_init<<<ng, blk>>>(x, W1 + 0 * FIN * HID);
    k_prop10<<<nw, blk>>>(T0, nullptr, T1, 1.0f);             // T1 = S T0
    k_l1_node<<<ng, blk>>>(T1, W1 + 1 * FIN * HID);
    k_prop10<<<nw, blk>>>(T1, T0, T2, 2.0f);                  // T2 = 2S T1 - T0
    k_l1_node<<<ng, blk>>>(T2, W1 + 2 * FIN * HID);
    k_prop10<<<nw, blk>>>(T2, T1, T0, 2.0f);                  // T3 (into T0)
    k_l1_node<<<ng, blk>>>(T0, W1 + 3 * FIN * HID);
    k_prop10<<<nw, blk>>>(T0, T2, T1, 2.0f);                  // T4 (into T1)
    k_l1_final<<<ng, blk>>>(T1, W1 + 4 * FIN * HID, b1, W2 + 0 * HID * HID);

    // ---- layer 2 (dim 30, stride 32) ----
    k_prop30<<<nw, blk>>>(A2, nullptr, B2, 1.0f);             // T1
    k_l2_node<<<ng, blk>>>(B2, W2 + 1 * HID * HID);
    k_prop30<<<nw, blk>>>(B2, A2, C2, 2.0f);                  // T2
    k_l2_node<<<ng, blk>>>(C2, W2 + 2 * HID * HID);
    k_prop30<<<nw, blk>>>(C2, B2, A2, 2.0f);                  // T3 (into A2)
    k_l2_node<<<ng, blk>>>(A2, W2 + 3 * HID * HID);
    k_prop30<<<nw, blk>>>(A2, C2, B2, 2.0f);                  // T4 (into B2)
    k_l2_final<<<ng, blk>>>(B2, W2 + 4 * HID * HID, b2, Wl, bl, out);
}

// round 10
// speedup vs baseline: 2.7819x; 1.0279x over previous
#include <cuda_runtime.h>
#include <cuda_fp16.h>
#include <cstddef>

#define NN   100000
#define NE   3200000
#define FIN  10
#define HID  30
#define NCLS 4
#define SH1  16   // layer-1 T row stride in halves (10 -> 16 = 32B)
#define SH2  32   // layer-2 T row stride in halves (30 -> 32 = 64B)
#define S2   32   // fp32 accumulator row stride (floats)

#define SCAN_BS 512
#define SCAN_NB ((NN + SCAN_BS - 1) / SCAN_BS)   // 196

// ---------------- scratch (static device globals) ---------------------------
__device__ __align__(16) float  g_deg[NN];
__device__ __align__(16) int    g_cnt[NN];
__device__ __align__(16) int    g_rs[NN + 1];
__device__ __align__(16) int    g_cur[NN];
__device__ __align__(16) int    g_bsum[SCAN_NB];
__device__ __align__(16) int    g_boff[SCAN_NB];
__device__ __align__(16) int2   g_recs[NE];      // {src, norm bits} sorted by dst
__device__ __align__(16) __half g_T0[NN * SH1];
__device__ __align__(16) __half g_T1[NN * SH1];
__device__ __align__(16) __half g_T2[NN * SH1];
__device__ __align__(16) __half g_A2[NN * SH2];
__device__ __align__(16) __half g_B2[NN * SH2];
__device__ __align__(16) __half g_C2[NN * SH2];
__device__ __align__(16) float  g_O1[NN * S2];
__device__ __align__(16) float  g_O2[NN * S2];

// ---------------- half pack/unpack helpers -----------------------------------
__device__ __forceinline__ void acc8(float* acc, uint4 v, float c) {
    const __half2* hp = (const __half2*)&v;
#pragma unroll
    for (int k = 0; k < 4; k++) {
        float2 f = __half22float2(hp[k]);
        acc[2 * k]     += c * f.x;
        acc[2 * k + 1] += c * f.y;
    }
}
__device__ __forceinline__ void unpack8(float* dst, uint4 v) {
    const __half2* hp = (const __half2*)&v;
#pragma unroll
    for (int k = 0; k < 4; k++) {
        float2 f = __half22float2(hp[k]);
        dst[2 * k] = f.x; dst[2 * k + 1] = f.y;
    }
}
__device__ __forceinline__ uint4 pack8(const float* a) {
    uint4 r;
    __half2* hp = (__half2*)&r;
#pragma unroll
    for (int k = 0; k < 4; k++) hp[k] = __floats2half2_rn(a[2 * k], a[2 * k + 1]);
    return r;
}

// ---------------- degree + histogram -----------------------------------------
__global__ void k_zero() {
    int i = blockIdx.x * blockDim.x + threadIdx.x;
    if (i < NN) { g_deg[i] = 0.f; g_cnt[i] = 0; }
}

__global__ void k_deg(const int* __restrict__ src, const int* __restrict__ dst,
                      const float* __restrict__ w) {
    int e = blockIdx.x * blockDim.x + threadIdx.x;
    if (e >= NE) return;
    int s = src[e], d = dst[e];
    if (s != d) atomicAdd(&g_deg[s], w[e]);
    atomicAdd(&g_cnt[d], 1);
}

// ---------------- CSR build: 2-level exclusive scan --------------------------
__global__ void k_scan1() {
    __shared__ int sh[SCAN_BS];
    int tid = threadIdx.x;
    int i = blockIdx.x * SCAN_BS + tid;
    int v = (i < NN) ? g_cnt[i] : 0;
    sh[tid] = v;
    __syncthreads();
#pragma unroll
    for (int ofs = 1; ofs < SCAN_BS; ofs <<= 1) {
        int t = (tid >= ofs) ? sh[tid - ofs] : 0;
        __syncthreads();
        sh[tid] += t;
        __syncthreads();
    }
    if (i < NN) g_rs[i] = sh[tid] - v;
    if (tid == SCAN_BS - 1) g_bsum[blockIdx.x] = sh[tid];
}

__global__ void k_scan2() {
    __shared__ int sh[256];
    int tid = threadIdx.x;
    int v = (tid < SCAN_NB) ? g_bsum[tid] : 0;
    sh[tid] = v;
    __syncthreads();
#pragma unroll
    for (int ofs = 1; ofs < 256; ofs <<= 1) {
        int t = (tid >= ofs) ? sh[tid - ofs] : 0;
        __syncthreads();
        sh[tid] += t;
        __syncthreads();
    }
    if (tid < SCAN_NB) g_boff[tid] = sh[tid] - v;
}

__global__ void k_scan3() {
    int i = blockIdx.x * blockDim.x + threadIdx.x;
    if (i < NN) {
        int r = g_rs[i] + g_boff[i / SCAN_BS];
        g_rs[i] = r;
        g_cur[i] = r;
    }
    if (i == 0) g_rs[NN] = NE;
}

// ---------------- fused norm + record scatter --------------------------------
__global__ void k_normbuild(const int* __restrict__ src, const int* __restrict__ dst,
                            const float* __restrict__ w) {
    int e = blockIdx.x * blockDim.x + threadIdx.x;
    if (e >= NE) return;
    int s = src[e], d = dst[e];
    float we = (s == d) ? 0.f : w[e];
    float ds = g_deg[s], dd = g_deg[d];
    float is = (ds > 0.f) ? rsqrtf(ds) : 0.f;
    float id = (dd > 0.f) ? rsqrtf(dd) : 0.f;
    float norm = -is * we * id;
    int p = atomicAdd(&g_cur[d], 1);
    g_recs[p] = make_int2(s, __float_as_int(norm));
}

// ---------------- layer 1 init: T0 = half(pad(x)), O1 = x @ W1[0] ------------
__global__ void k_l1_init(const float* __restrict__ x, const float* __restrict__ W0) {
    __shared__ __align__(16) float sWp[FIN * 32];
    for (int i = threadIdx.x; i < FIN * 32; i += blockDim.x) {
        int r = i >> 5, c = i & 31;
        sWp[i] = (c < HID) ? W0[r * HID + c] : 0.f;
    }
    __syncthreads();
    int n = blockIdx.x * blockDim.x + threadIdx.x;
    if (n >= NN) return;
    float t[FIN];
    const float* xr = x + (size_t)n * FIN;
#pragma unroll
    for (int i = 0; i < FIN; i++) t[i] = xr[i];
    float tp[16];
#pragma unroll
    for (int i = 0; i < FIN; i++) tp[i] = t[i];
#pragma unroll
    for (int i = FIN; i < 16; i++) tp[i] = 0.f;
    uint4* a = (uint4*)(g_T0 + (size_t)n * SH1);
    a[0] = pack8(tp);
    a[1] = pack8(tp + 8);
    float4 acc[8];
#pragma unroll
    for (int q = 0; q < 8; q++) acc[q] = make_float4(0.f, 0.f, 0.f, 0.f);
#pragma unroll
    for (int i = 0; i < FIN; i++) {
        const float4* wr = (const float4*)(sWp + i * 32);
#pragma unroll
        for (int q = 0; q < 8; q++) {
            float4 wv = wr[q];
            acc[q].x += t[i] * wv.x; acc[q].y += t[i] * wv.y;
            acc[q].z += t[i] * wv.z; acc[q].w += t[i] * wv.w;
        }
    }
    float4* o = (float4*)(g_O1 + (size_t)n * S2);
#pragma unroll
    for (int q = 0; q < 8; q++) o[q] = acc[q];
}

// ---------------- warp-per-node CSR gather props (fp16 T storage) ------------
// prop10: rows of 16 halves (2 uint4 slots). 16 edge-subgroups x 2 lanes.
__global__ void k_prop10(const __half* __restrict__ hin, const __half* __restrict__ Tprev,
                         __half* __restrict__ hout, float scale) {
    int warp = (blockIdx.x * blockDim.x + threadIdx.x) >> 5;
    int lane = threadIdx.x & 31;
    if (warp >= NN) return;
    int n = warp;
    int off = lane & 1;          // uint4 slot (8 halves)
    int sub = lane >> 1;         // 0..15 edge subgroup
    int s = g_rs[n], e = g_rs[n + 1];
    float acc[8] = {0.f, 0.f, 0.f, 0.f, 0.f, 0.f, 0.f, 0.f};
    int i = s + sub;
    for (; i + 16 < e; i += 32) {
        int2 r0 = g_recs[i], r1 = g_recs[i + 16];
        float c0 = __int_as_float(r0.y) * scale;
        float c1 = __int_as_float(r1.y) * scale;
        uint4 v0 = *(const uint4*)(hin + ((size_t)r0.x << 4) + (off << 3));
        uint4 v1 = *(const uint4*)(hin + ((size_t)r1.x << 4) + (off << 3));
        acc8(acc, v0, c0);
        acc8(acc, v1, c1);
    }
    for (; i < e; i += 16) {
        int2 r = g_recs[i];
        float c = __int_as_float(r.y) * scale;
        uint4 v = *(const uint4*)(hin + ((size_t)r.x << 4) + (off << 3));
        acc8(acc, v, c);
    }
#pragma unroll
    for (int m = 2; m <= 16; m <<= 1) {
#pragma unroll
        for (int k = 0; k < 8; k++)
            acc[k] += __shfl_xor_sync(0xFFFFFFFF, acc[k], m);
    }
    if (lane < 2) {
        if (Tprev) {
            uint4 tv = *(const uint4*)(Tprev + ((size_t)n << 4) + (lane << 3));
            float tf[8];
            unpack8(tf, tv);
#pragma unroll
            for (int k = 0; k < 8; k++) acc[k] -= tf[k];
        }
        *(uint4*)(hout + ((size_t)n << 4) + (lane << 3)) = pack8(acc);
    }
}

// prop30: rows of 32 halves (4 uint4 slots). 8 edge-subgroups x 4 lanes.
__global__ void k_prop30(const __half* __restrict__ hin, const __half* __restrict__ Tprev,
                         __half* __restrict__ hout, float scale) {
    int warp = (blockIdx.x * blockDim.x + threadIdx.x) >> 5;
    int lane = threadIdx.x & 31;
    if (warp >= NN) return;
    int n = warp;
    int off = lane & 3;          // uint4 slot (8 halves)
    int sub = lane >> 2;         // 0..7 edge subgroup
    int s = g_rs[n], e = g_rs[n + 1];
    float acc[8] = {0.f, 0.f, 0.f, 0.f, 0.f, 0.f, 0.f, 0.f};
    int i = s + sub;
    for (; i + 8 < e; i += 16) {
        int2 r0 = g_recs[i], r1 = g_recs[i + 8];
        float c0 = __int_as_float(r0.y) * scale;
        float c1 = __int_as_float(r1.y) * scale;
        uint4 v0 = *(const uint4*)(hin + ((size_t)r0.x << 5) + (off << 3));
        uint4 v1 = *(const uint4*)(hin + ((size_t)r1.x << 5) + (off << 3));
        acc8(acc, v0, c0);
        acc8(acc, v1, c1);
    }
    if (i < e) {
        int2 r = g_recs[i];
        float c = __int_as_float(r.y) * scale;
        uint4 v = *(const uint4*)(hin + ((size_t)r.x << 5) + (off << 3));
        acc8(acc, v, c);
    }
#pragma unroll
    for (int m = 4; m <= 16; m <<= 1) {
#pragma unroll
        for (int k = 0; k < 8; k++)
            acc[k] += __shfl_xor_sync(0xFFFFFFFF, acc[k], m);
    }
    if (lane < 4) {
        if (Tprev) {
            uint4 tv = *(const uint4*)(Tprev + ((size_t)n << 5) + (lane << 3));
            float tf[8];
            unpack8(tf, tv);
#pragma unroll
            for (int k = 0; k < 8; k++) acc[k] -= tf[k];
        }
        *(uint4*)(hout + ((size_t)n << 5) + (lane << 3)) = pack8(acc);
    }
}

// ---------------- node matvec steps (half T in, fp32 O accumulate) -----------
__global__ void k_l1_node(const __half* __restrict__ Tnew, const float* __restrict__ Wk) {
    __shared__ __align__(16) float sWp[FIN * 32];
    for (int i = threadIdx.x; i < FIN * 32; i += blockDim.x) {
        int r = i >> 5, c = i & 31;
        sWp[i] = (c < HID) ? Wk[r * HID + c] : 0.f;
    }
    __syncthreads();
    int n = blockIdx.x * blockDim.x + threadIdx.x;
    if (n >= NN) return;
    const uint4* tr = (const uint4*)(Tnew + (size_t)n * SH1);
    float t[16];
    unpack8(t, tr[0]);
    unpack8(t + 8, tr[1]);
    float4* o = (float4*)(g_O1 + (size_t)n * S2);
    float4 acc[8];
#pragma unroll
    for (int q = 0; q < 8; q++) acc[q] = o[q];
#pragma unroll
    for (int i = 0; i < FIN; i++) {
        const float4* wr = (const float4*)(sWp + i * 32);
#pragma unroll
        for (int q = 0; q < 8; q++) {
            float4 wv = wr[q];
            acc[q].x += t[i] * wv.x; acc[q].y += t[i] * wv.y;
            acc[q].z += t[i] * wv.z; acc[q].w += t[i] * wv.w;
        }
    }
#pragma unroll
    for (int q = 0; q < 8; q++) o[q] = acc[q];
}

__global__ void k_l2_node(const __half* __restrict__ Tnew, const float* __restrict__ Wk) {
    __shared__ __align__(16) float sWp[HID * 32];
    for (int i = threadIdx.x; i < HID * 32; i += blockDim.x) {
        int r = i >> 5, c = i & 31;
        sWp[i] = (c < HID) ? Wk[r * HID + c] : 0.f;
    }
    __syncthreads();
    int n = blockIdx.x * blockDim.x + threadIdx.x;
    if (n >= NN) return;
    const uint4* tr = (const uint4*)(Tnew + (size_t)n * SH2);
    float t[32];
#pragma unroll
    for (int q = 0; q < 4; q++) unpack8(t + 8 * q, tr[q]);
    float4* o = (float4*)(g_O2 + (size_t)n * S2);
    float4 acc[8];
#pragma unroll
    for (int q = 0; q < 8; q++) acc[q] = o[q];
#pragma unroll
    for (int i = 0; i < HID; i++) {
        const float4* wr = (const float4*)(sWp + i * 32);
#pragma unroll
        for (int q = 0; q < 8; q++) {
            float4 wv = wr[q];
            acc[q].x += t[i] * wv.x; acc[q].y += t[i] * wv.y;
            acc[q].z += t[i] * wv.z; acc[q].w += t[i] * wv.w;
        }
    }
#pragma unroll
    for (int q = 0; q < 8; q++) o[q] = acc[q];
}

// -------- layer-1 final: h=relu(O1+T4@W1[4]+b1); A2=half(h), O2=h@W2[0] ------
__global__ void k_l1_final(const __half* __restrict__ Tnew,
                           const float* __restrict__ W14, const float* __restrict__ b1,
                           const float* __restrict__ W20) {
    __shared__ __align__(16) float sW4p[FIN * 32];
    __shared__ __align__(16) float sW0p[HID * 32];
    __shared__ float sb[HID];
    for (int i = threadIdx.x; i < FIN * 32; i += blockDim.x) {
        int r = i >> 5, c = i & 31;
        sW4p[i] = (c < HID) ? W14[r * HID + c] : 0.f;
    }
    for (int i = threadIdx.x; i < HID * 32; i += blockDim.x) {
        int r = i >> 5, c = i & 31;
        sW0p[i] = (c < HID) ? W20[r * HID + c] : 0.f;
    }
    for (int i = threadIdx.x; i < HID; i += blockDim.x) sb[i] = b1[i];
    __syncthreads();
    int n = blockIdx.x * blockDim.x + threadIdx.x;
    if (n >= NN) return;
    const uint4* tr = (const uint4*)(Tnew + (size_t)n * SH1);
    float t[16];
    unpack8(t, tr[0]);
    unpack8(t + 8, tr[1]);
    const float4* o1 = (const float4*)(g_O1 + (size_t)n * S2);
    float4 acc[8];
#pragma unroll
    for (int q = 0; q < 8; q++) acc[q] = o1[q];
#pragma unroll
    for (int i = 0; i < FIN; i++) {
        const float4* wr = (const float4*)(sW4p + i * 32);
#pragma unroll
        for (int q = 0; q < 8; q++) {
            float4 wv = wr[q];
            acc[q].x += t[i] * wv.x; acc[q].y += t[i] * wv.y;
            acc[q].z += t[i] * wv.z; acc[q].w += t[i] * wv.w;
        }
    }
    float h[32];
#pragma unroll
    for (int j = 0; j < HID; j++) {
        float v = ((const float*)acc)[j];
        h[j] = fmaxf(v + sb[j], 0.f);
    }
    h[30] = 0.f; h[31] = 0.f;
    uint4* a2 = (uint4*)(g_A2 + (size_t)n * SH2);
#pragma unroll
    for (int q = 0; q < 4; q++) a2[q] = pack8(h + 8 * q);
    float4 acc2[8];
#pragma unroll
    for (int q = 0; q < 8; q++) acc2[q] = make_float4(0.f, 0.f, 0.f, 0.f);
#pragma unroll
    for (int i = 0; i < HID; i++) {
        const float4* wr = (const float4*)(sW0p + i * 32);
#pragma unroll
        for (int q = 0; q < 8; q++) {
            float4 wv = wr[q];
            acc2[q].x += h[i] * wv.x; acc2[q].y += h[i] * wv.y;
            acc2[q].z += h[i] * wv.z; acc2[q].w += h[i] * wv.w;
        }
    }
    float4* o2 = (float4*)(g_O2 + (size_t)n * S2);
#pragma unroll
    for (int q = 0; q < 8; q++) o2[q] = acc2[q];
}

// -------- layer-2 final + head: out = relu(O2+T4@W2[4]+b2) @ Wl + bl ---------
__global__ void k_l2_final(const __half* __restrict__ Tnew,
                           const float* __restrict__ W24, const float* __restrict__ b2,
                           const float* __restrict__ Wl, const float* __restrict__ bl,
                           float* __restrict__ out) {
    __shared__ __align__(16) float sW4p[HID * 32];
    __shared__ float sWl[HID * NCLS];
    __shared__ float sb2[HID];
    __shared__ float sbl[NCLS];
    for (int i = threadIdx.x; i < HID * 32; i += blockDim.x) {
        int r = i >> 5, c = i & 31;
        sW4p[i] = (c < HID) ? W24[r * HID + c] : 0.f;
    }
    for (int i = threadIdx.x; i < HID * NCLS; i += blockDim.x) sWl[i] = Wl[i];
    for (int i = threadIdx.x; i < HID; i += blockDim.x) sb2[i] = b2[i];
    for (int i = threadIdx.x; i < NCLS; i += blockDim.x) sbl[i] = bl[i];
    __syncthreads();
    int n = blockIdx.x * blockDim.x + threadIdx.x;
    if (n >= NN) return;
    const uint4* tr = (const uint4*)(Tnew + (size_t)n * SH2);
    float t[32];
#pragma unroll
    for (int q = 0; q < 4; q++) unpack8(t + 8 * q, tr[q]);
    const float4* o2 = (const float4*)(g_O2 + (size_t)n * S2);
    float4 acc[8];
#pragma unroll
    for (int q = 0; q < 8; q++) acc[q] = o2[q];
#pragma unroll
    for (int i = 0; i < HID; i++) {
        const float4* wr = (const float4*)(sW4p + i * 32);
#pragma unroll
        for (int q = 0; q < 8; q++) {
            float4 wv = wr[q];
            acc[q].x += t[i] * wv.x; acc[q].y += t[i] * wv.y;
            acc[q].z += t[i] * wv.z; acc[q].w += t[i] * wv.w;
        }
    }
    float h[HID];
#pragma unroll
    for (int j = 0; j < HID; j++) {
        float v = ((const float*)acc)[j];
        h[j] = fmaxf(v + sb2[j], 0.f);
    }
    float r[NCLS];
#pragma unroll
    for (int c = 0; c < NCLS; c++) r[c] = sbl[c];
#pragma unroll
    for (int j = 0; j < HID; j++) {
#pragma unroll
        for (int c = 0; c < NCLS; c++) r[c] += h[j] * sWl[j * NCLS + c];
    }
    *(float4*)(out + (size_t)n * NCLS) = make_float4(r[0], r[1], r[2], r[3]);
}

// ---------------- launch -----------------------------------------------------
extern "C" void kernel_launch(void* const* d_in, const int* in_sizes, int n_in,
                              void* d_out, int out_size) {
    const float* x  = (const float*)d_in[0];
    const int*   ei = (const int*)d_in[1];
    const float* ew = (const float*)d_in[2];
    const float* W1 = (const float*)d_in[3];
    const float* b1 = (const float*)d_in[4];
    const float* W2 = (const float*)d_in[5];
    const float* b2 = (const float*)d_in[6];
    const float* Wl = (const float*)d_in[7];
    const float* bl = (const float*)d_in[8];
    float* out = (float*)d_out;

    const int* src = ei;
    const int* dst = ei + NE;

    __half *T0, *T1, *T2, *A2, *B2, *C2;
    cudaGetSymbolAddress((void**)&T0, g_T0);
    cudaGetSymbolAddress((void**)&T1, g_T1);
    cudaGetSymbolAddress((void**)&T2, g_T2);
    cudaGetSymbolAddress((void**)&A2, g_A2);
    cudaGetSymbolAddress((void**)&B2, g_B2);
    cudaGetSymbolAddress((void**)&C2, g_C2);

    dim3 blk(256);
    dim3 ng((NN + 255) / 256);
    dim3 eg((NE + 255) / 256);
    dim3 nw((NN * 32 + 255) / 256);   // warp-per-node prop grids

    // CSR build
    k_zero<<<ng, blk>>>();
    k_deg<<<eg, blk>>>(src, dst, ew);
    k_scan1<<<SCAN_NB, SCAN_BS>>>();
    k_scan2<<<1, 256>>>();
    k_scan3<<<ng, blk>>>();
    k_normbuild<<<eg, blk>>>(src, dst, ew);

    // ---- layer 1 (dim 10, half rows of 16) ----
    k_l1_init<<<ng, blk>>>(x, W1 + 0 * FIN * HID);
    k_prop10<<<nw, blk>>>(T0, nullptr, T1, 1.0f);             // T1 = S T0
    k_l1_node<<<ng, blk>>>(T1, W1 + 1 * FIN * HID);
    k_prop10<<<nw, blk>>>(T1, T0, T2, 2.0f);                  // T2 = 2S T1 - T0
    k_l1_node<<<ng, blk>>>(T2, W1 + 2 * FIN * HID);
    k_prop10<<<nw, blk>>>(T2, T1, T0, 2.0f);                  // T3 (into T0)
    k_l1_node<<<ng, blk>>>(T0, W1 + 3 * FIN * HID);
    k_prop10<<<nw, blk>>>(T0, T2, T1, 2.0f);                  // T4 (into T1)
    k_l1_final<<<ng, blk>>>(T1, W1 + 4 * FIN * HID, b1, W2 + 0 * HID * HID);

    // ---- layer 2 (dim 30, half rows of 32) ----
    k_prop30<<<nw, blk>>>(A2, nullptr, B2, 1.0f);             // T1
    k_l2_node<<<ng, blk>>>(B2, W2 + 1 * HID * HID);
    k_prop30<<<nw, blk>>>(B2, A2, C2, 2.0f);                  // T2
    k_l2_node<<<ng, blk>>>(C2, W2 + 2 * HID * HID);
    k_prop30<<<nw, blk>>>(C2, B2, A2, 2.0f);                  // T3 (into A2)
    k_l2_node<<<ng, blk>>>(A2, W2 + 3 * HID * HID);
    k_prop30<<<nw, blk>>>(A2, C2, B2, 2.0f);                  // T4 (into B2)
    k_l2_final<<<ng, blk>>>(B2, W2 + 4 * HID * HID, b2, Wl, bl, out);
}